// round 3
// baseline (speedup 1.0000x reference)
#include <cuda_runtime.h>

#define TOK 8192
#define SEQ 2048
#define DIM 512
#define NH  8
#define HDM 64
#define NL  4
#define FF  200
#define NB  4

typedef unsigned long long u64t;

// ---------------- device scratch (allocation-free) ----------------
__device__ float g_x[TOK*DIM];
__device__ float g_q[TOK*DIM];
__device__ float g_k[TOK*DIM];
__device__ float g_v[TOK*DIM];
__device__ float g_y[TOK*DIM];
__device__ float g_t[TOK*DIM];
__device__ float g_h[TOK*FF];

// ---------------- packed f32x2 helpers ----------------
__device__ __forceinline__ void fma2(u64t& d, u64t a, u64t b) {
    asm volatile("fma.rn.f32x2 %0, %1, %2, %0;" : "+l"(d) : "l"(a), "l"(b));
}
__device__ __forceinline__ void mul2(u64t& d, u64t a, u64t b) {
    asm volatile("mul.rn.f32x2 %0, %1, %2;" : "=l"(d) : "l"(a), "l"(b));
}
__device__ __forceinline__ void lds2(u64t& a, u64t& b, unsigned addr) {
    asm volatile("ld.shared.v2.b64 {%0,%1}, [%2];" : "=l"(a), "=l"(b) : "r"(addr));
}
__device__ __forceinline__ void unpack2(float& lo, float& hi, u64t p) {
    asm volatile("mov.b64 {%0,%1}, %2;" : "=f"(lo), "=f"(hi) : "l"(p));
}
__device__ __forceinline__ void pack2(u64t& p, float lo, float hi) {
    asm volatile("mov.b64 %0, {%1,%2};" : "=l"(p) : "f"(lo), "f"(hi));
}
__device__ __forceinline__ unsigned su32(const void* p) {
    return (unsigned)__cvta_generic_to_shared(p);
}

// ---------------- fast exp2 on the FMA pipe (input <= 0) ----------------
__device__ __forceinline__ float exp2_fast(float t) {
    t = fmaxf(t, -126.0f);
    float z = t + 12582912.0f;
    int   ii = __float_as_int(z);
    float n  = z - 12582912.0f;
    float f  = t - n;
    float p  =            1.535336188319500e-4f;
    p = fmaf(p, f, 1.339887440266574e-3f);
    p = fmaf(p, f, 9.618437357674640e-3f);
    p = fmaf(p, f, 5.550332471162809e-2f);
    p = fmaf(p, f, 2.402264791363012e-1f);
    p = fmaf(p, f, 6.931472028550421e-1f);
    p = fmaf(p, f, 1.0f);
    return __int_as_float(__float_as_int(p) + (ii << 23));
}

// ---------------- positional encoding ----------------
__global__ void posenc_kernel(const float* __restrict__ f, float* __restrict__ x) {
    int idx = blockIdx.x * blockDim.x + threadIdx.x;
    if (idx >= TOK*DIM) return;
    int d = idx & (DIM-1);
    int s = (idx / DIM) & (SEQ-1);
    int i2 = d & ~1;
    float div = expf((float)i2 * (-9.210340371976184f / (float)DIM));
    float ang = (float)s * div;
    float pe = (d & 1) ? cosf(ang) : sinf(ang);
    x[idx] = f[idx] + pe;
}

// ---------------- SGEMM 128x128x8, FFMA2 microkernel ----------------
// As stored duplicated+transposed: As[k][2m],As[k][2m+1] = A[m][k]
template<int RELU>
__global__ __launch_bounds__(256, 2)
void gemm128_kernel(const float* __restrict__ A, const float* __restrict__ B,
                    const float* __restrict__ bias, float* __restrict__ C,
                    int M, int K, int Nn) {
    __shared__ float As[8][264];   // dup'd A^T tile (256 used + pad)
    __shared__ float Bs[8][132];
    int tid = threadIdx.x;
    int tx = tid & 15, ty = tid >> 4;
    int m0 = blockIdx.y * 128, n0 = blockIdx.x * 128;

    int a_row = tid >> 1;                // 0..127
    int a_kg  = (tid & 1) * 4;           // 0 or 4
    int b_k   = tid >> 5;                // 0..7
    int b_col = (tid & 31) * 4;          // 0..124

    unsigned aBase = su32(&As[0][0]);
    unsigned bBase = su32(&Bs[0][0]);

    u64t acc[8][4] = {};                 // i (8 rows) x jp (4 col-pairs)

    for (int k0 = 0; k0 < K; k0 += 8) {
        float4 av = *(const float4*)&A[(size_t)(m0 + a_row) * K + k0 + a_kg];
        float4 bv;
        int gn = n0 + b_col;
        if (gn + 3 < Nn) {
            bv = *(const float4*)&B[(size_t)(k0 + b_k) * Nn + gn];
        } else {
            const float* br = &B[(size_t)(k0 + b_k) * Nn];
            bv.x = (gn + 0 < Nn) ? br[gn + 0] : 0.f;
            bv.y = (gn + 1 < Nn) ? br[gn + 1] : 0.f;
            bv.z = (gn + 2 < Nn) ? br[gn + 2] : 0.f;
            bv.w = (gn + 3 < Nn) ? br[gn + 3] : 0.f;
        }
        // dup'd transpose stores for A
        As[a_kg + 0][2*a_row] = av.x;  As[a_kg + 0][2*a_row + 1] = av.x;
        As[a_kg + 1][2*a_row] = av.y;  As[a_kg + 1][2*a_row + 1] = av.y;
        As[a_kg + 2][2*a_row] = av.z;  As[a_kg + 2][2*a_row + 1] = av.z;
        As[a_kg + 3][2*a_row] = av.w;  As[a_kg + 3][2*a_row + 1] = av.w;
        *(float4*)&Bs[b_k][b_col] = bv;
        __syncthreads();

        #pragma unroll
        for (int k = 0; k < 8; k++) {
            u64t ad[8], bp[4];
            unsigned a0 = aBase + (unsigned)(k*264 + 8*ty) * 4u;
            lds2(ad[0], ad[1], a0);
            lds2(ad[2], ad[3], a0 + 16u);
            unsigned a1 = aBase + (unsigned)(k*264 + 128 + 8*ty) * 4u;
            lds2(ad[4], ad[5], a1);
            lds2(ad[6], ad[7], a1 + 16u);
            unsigned b0 = bBase + (unsigned)(k*132 + tx*4) * 4u;
            lds2(bp[0], bp[1], b0);
            lds2(bp[2], bp[3], b0 + 256u);   // col +64
            #pragma unroll
            for (int i = 0; i < 8; i++)
                #pragma unroll
                for (int jp = 0; jp < 4; jp++)
                    fma2(acc[i][jp], ad[i], bp[jp]);
        }
        __syncthreads();
    }

    // epilogue
    #pragma unroll
    for (int i = 0; i < 8; i++) {
        int gm = m0 + ((i < 4) ? (ty * 4 + i) : (64 + ty * 4 + i - 4));
        #pragma unroll
        for (int jp = 0; jp < 4; jp++) {
            float lo, hi;
            unpack2(lo, hi, acc[i][jp]);
            int jbase = (jp < 2) ? (tx * 4 + jp * 2) : (64 + tx * 4 + (jp - 2) * 2);
            int gn0 = n0 + jbase, gn1 = gn0 + 1;
            if (gn0 < Nn) {
                float vv = lo + bias[gn0];
                if (RELU) vv = fmaxf(vv, 0.f);
                C[(size_t)gm * Nn + gn0] = vv;
            }
            if (gn1 < Nn) {
                float vv = hi + bias[gn1];
                if (RELU) vv = fmaxf(vv, 0.f);
                C[(size_t)gm * Nn + gn1] = vv;
            }
        }
    }
}

// ---------------- flash attention, FFMA2 microkernels ----------------
// BQ=128, BK=64, 256 threads, 8 rows x 4 cols per thread (cols packed as 2 pairs)
#define QD_STR 260   // dup'd Q^T: Qd[d][2r] (+pad)
#define KT_STR 68    // K^T: Kt[d][c]
#define VS_STR 68    // V:   Vs[c][d]
#define PD_STR 256   // dup'd P^T, swizzled: Pd[c][(2r + f(c)) & 255]
#define ATTN_SMEM ((64*QD_STR + 64*KT_STR + 64*VS_STR + 64*PD_STR) * 4)

__global__ __launch_bounds__(256)
void attn_kernel(const float* __restrict__ q, const float* __restrict__ k,
                 const float* __restrict__ v, float* __restrict__ y) {
    extern __shared__ float sm[];
    float* Qd = sm;                       // 64 x 260
    float* Kt = Qd + 64 * QD_STR;         // 64 x 68
    float* Vs = Kt + 64 * KT_STR;         // 64 x 68
    float* Pd = Vs + 64 * VS_STR;         // 64 x 256

    unsigned qBase = su32(Qd);
    unsigned kBase = su32(Kt);
    unsigned vBase = su32(Vs);
    unsigned pBase = su32(Pd);

    int tid = threadIdx.x;
    int tx = tid & 15, ty = tid >> 4;
    int qt_blk = blockIdx.x, h = blockIdx.y, n = blockIdx.z;
    const float SCALE_LOG2E = 0.125f * 1.4426950408889634f;

    int qbase = n * SEQ + qt_blk * 128;
    int hoff = h * HDM;

    // load Q tile dup'd+transposed: Qd[d][2r],Qd[d][2r+1] = Q[r][d]
    #pragma unroll
    for (int it = 0; it < 8; it++) {
        int idx4 = tid + it * 256;           // 128 rows x 16 d-chunks
        int row = idx4 >> 4;
        int d = (idx4 & 15) * 4;
        float4 qv = *(const float4*)&q[(size_t)(qbase + row) * DIM + hoff + d];
        Qd[(d + 0) * QD_STR + 2*row] = qv.x;  Qd[(d + 0) * QD_STR + 2*row + 1] = qv.x;
        Qd[(d + 1) * QD_STR + 2*row] = qv.y;  Qd[(d + 1) * QD_STR + 2*row + 1] = qv.y;
        Qd[(d + 2) * QD_STR + 2*row] = qv.z;  Qd[(d + 2) * QD_STR + 2*row + 1] = qv.z;
        Qd[(d + 3) * QD_STR + 2*row] = qv.w;  Qd[(d + 3) * QD_STR + 2*row + 1] = qv.w;
    }

    u64t O[8][2] = {};                   // 8 rows x 2 d-pairs
    float mrow[8], lrow[8] = {};
    #pragma unroll
    for (int i = 0; i < 8; i++) mrow[i] = -1e30f;
    __syncthreads();

    for (int kt = 0; kt < SEQ / 64; kt++) {
        int kbase = n * SEQ + kt * 64;
        #pragma unroll
        for (int it = 0; it < 4; it++) {
            int idx4 = tid + it * 256;       // 64 rows x 16 d-chunks
            int r = idx4 >> 4;
            int d = (idx4 & 15) * 4;
            float4 kv = *(const float4*)&k[(size_t)(kbase + r) * DIM + hoff + d];
            Kt[(d + 0) * KT_STR + r] = kv.x;
            Kt[(d + 1) * KT_STR + r] = kv.y;
            Kt[(d + 2) * KT_STR + r] = kv.z;
            Kt[(d + 3) * KT_STR + r] = kv.w;
            float4 vv = *(const float4*)&v[(size_t)(kbase + r) * DIM + hoff + d];
            *(float4*)&Vs[r * VS_STR + d] = vv;
        }
        __syncthreads();

        // S = Q K^T : s_p[i][jp] packed over col pairs
        u64t s_p[8][2] = {};
        #pragma unroll 8
        for (int d = 0; d < 64; d++) {
            u64t ad[8], bp[2];
            unsigned a0 = qBase + (unsigned)(d * QD_STR + 16*ty) * 4u;
            lds2(ad[0], ad[1], a0);
            lds2(ad[2], ad[3], a0 + 16u);
            lds2(ad[4], ad[5], a0 + 32u);
            lds2(ad[6], ad[7], a0 + 48u);
            lds2(bp[0], bp[1], kBase + (unsigned)(d * KT_STR + tx*4) * 4u);
            #pragma unroll
            for (int i = 0; i < 8; i++) {
                fma2(s_p[i][0], ad[i], bp[0]);
                fma2(s_p[i][1], ad[i], bp[1]);
            }
        }

        // online softmax (base-2), rows shared by 16 tx lanes
        float ps[8][4];
        #pragma unroll
        for (int i = 0; i < 8; i++) {
            float v0, v1, v2, v3;
            unpack2(v0, v1, s_p[i][0]);
            unpack2(v2, v3, s_p[i][1]);
            v0 *= SCALE_LOG2E; v1 *= SCALE_LOG2E; v2 *= SCALE_LOG2E; v3 *= SCALE_LOG2E;
            float mloc = fmaxf(fmaxf(v0, v1), fmaxf(v2, v3));
            #pragma unroll
            for (int off = 8; off; off >>= 1)
                mloc = fmaxf(mloc, __shfl_xor_sync(0xffffffffu, mloc, off));
            float newm = fmaxf(mrow[i], mloc);
            float corr = exp2_fast(mrow[i] - newm);
            mrow[i] = newm;
            float p0 = exp2_fast(v0 - newm);
            float p1 = exp2_fast(v1 - newm);
            float p2 = exp2_fast(v2 - newm);
            float p3 = exp2_fast(v3 - newm);
            float rs = (p0 + p1) + (p2 + p3);
            #pragma unroll
            for (int off = 8; off; off >>= 1)
                rs += __shfl_xor_sync(0xffffffffu, rs, off);
            lrow[i] = lrow[i] * corr + rs;
            u64t corrp;
            pack2(corrp, corr, corr);
            mul2(O[i][0], O[i][0], corrp);
            mul2(O[i][1], O[i][1], corrp);
            ps[i][0] = p0; ps[i][1] = p1; ps[i][2] = p2; ps[i][3] = p3;
        }

        // store P dup'd+transposed+swizzled: Pd[c][(2r + f(c)) & 255]
        {
            int fc = (tx & 7) << 2;          // f(c) for c = tx*4+j (depends on c>>2 = tx)
            #pragma unroll
            for (int j = 0; j < 4; j++) {
                int c = tx * 4 + j;
                unsigned rowb = pBase + (unsigned)(c * PD_STR) * 4u;
                #pragma unroll
                for (int g = 0; g < 4; g++) {
                    int col = (16 * ty + 4 * g + fc) & 255;
                    float4 pv = make_float4(ps[2*g][j], ps[2*g][j], ps[2*g+1][j], ps[2*g+1][j]);
                    *(float4*)((char*)sm + ((rowb - su32(sm)) + (unsigned)col * 4u)) = ((void)0, pv);
                }
            }
        }
        __syncthreads();

        // O += P V
        #pragma unroll 8
        for (int c = 0; c < 64; c++) {
            int fc = ((c >> 2) & 7) << 2;
            u64t ad[8], bp[2];
            unsigned abase = pBase + (unsigned)(c * PD_STR) * 4u;
            unsigned c0 = (unsigned)((16*ty + 0  + fc) & 255) * 4u;
            unsigned c1 = (unsigned)((16*ty + 4  + fc) & 255) * 4u;
            unsigned c2 = (unsigned)((16*ty + 8  + fc) & 255) * 4u;
            unsigned c3 = (unsigned)((16*ty + 12 + fc) & 255) * 4u;
            lds2(ad[0], ad[1], abase + c0);
            lds2(ad[2], ad[3], abase + c1);
            lds2(ad[4], ad[5], abase + c2);
            lds2(ad[6], ad[7], abase + c3);
            lds2(bp[0], bp[1], vBase + (unsigned)(c * VS_STR + tx*4) * 4u);
            #pragma unroll
            for (int i = 0; i < 8; i++) {
                fma2(O[i][0], ad[i], bp[0]);
                fma2(O[i][1], ad[i], bp[1]);
            }
        }
        __syncthreads();
    }

    // write out normalized
    #pragma unroll
    for (int i = 0; i < 8; i++) {
        float inv = 1.0f / lrow[i];
        float o0, o1, o2, o3;
        unpack2(o0, o1, O[i][0]);
        unpack2(o2, o3, O[i][1]);
        int row = qbase + ty * 8 + i;
        float4 ov = make_float4(o0 * inv, o1 * inv, o2 * inv, o3 * inv);
        *(float4*)&y[(size_t)row * DIM + hoff + tx * 4] = ov;
    }
}

// ---------------- fused residual + LayerNorm ----------------
__global__ void ln_kernel(const float* __restrict__ x, const float* __restrict__ r,
                          const float* __restrict__ w, const float* __restrict__ b,
                          float* __restrict__ out) {
    int row = blockIdx.x;
    int tid = threadIdx.x;
    const float* xr = x + (size_t)row * DIM;
    const float* rr = r + (size_t)row * DIM;
    float vals[4];
    float sum = 0.f;
    #pragma unroll
    for (int i = 0; i < 4; i++) {
        int d = tid + i*128;
        vals[i] = xr[d] + rr[d];
        sum += vals[i];
    }
    __shared__ float red1[4], red2[4];
    #pragma unroll
    for (int off = 16; off; off >>= 1) sum += __shfl_xor_sync(0xffffffffu, sum, off);
    if ((tid & 31) == 0) red1[tid >> 5] = sum;
    __syncthreads();
    sum = red1[0] + red1[1] + red1[2] + red1[3];
    float mean = sum * (1.f / DIM);
    float vs = 0.f;
    #pragma unroll
    for (int i = 0; i < 4; i++) {
        float dv = vals[i] - mean;
        vs += dv * dv;
    }
    #pragma unroll
    for (int off = 16; off; off >>= 1) vs += __shfl_xor_sync(0xffffffffu, vs, off);
    if ((tid & 31) == 0) red2[tid >> 5] = vs;
    __syncthreads();
    vs = red2[0] + red2[1] + red2[2] + red2[3];
    float rstd = rsqrtf(vs * (1.f / DIM) + 1e-5f);
    #pragma unroll
    for (int i = 0; i < 4; i++) {
        int d = tid + i*128;
        out[(size_t)row * DIM + d] = (vals[i] - mean) * rstd * w[d] + b[d];
    }
}

// ---------------- host ----------------
extern "C" void kernel_launch(void* const* d_in, const int* in_sizes, int n_in,
                              void* d_out, int out_size) {
    const float* features = (const float*)d_in[0];
    const float* Wq = (const float*)d_in[1];
    const float* bq = (const float*)d_in[2];
    const float* Wk = (const float*)d_in[3];
    const float* bk = (const float*)d_in[4];
    const float* Wv = (const float*)d_in[5];
    const float* bv = (const float*)d_in[6];
    const float* Wo = (const float*)d_in[7];
    const float* bo = (const float*)d_in[8];
    const float* W1 = (const float*)d_in[9];
    const float* b1 = (const float*)d_in[10];
    const float* W2 = (const float*)d_in[11];
    const float* b2 = (const float*)d_in[12];
    const float* ln1w = (const float*)d_in[13];
    const float* ln1b = (const float*)d_in[14];
    const float* ln2w = (const float*)d_in[15];
    const float* ln2b = (const float*)d_in[16];
    float* out = (float*)d_out;

    float *x, *q, *k, *v, *y, *t, *hbuf;
    cudaGetSymbolAddress((void**)&x, g_x);
    cudaGetSymbolAddress((void**)&q, g_q);
    cudaGetSymbolAddress((void**)&k, g_k);
    cudaGetSymbolAddress((void**)&v, g_v);
    cudaGetSymbolAddress((void**)&y, g_y);
    cudaGetSymbolAddress((void**)&t, g_t);
    cudaGetSymbolAddress((void**)&hbuf, g_h);

    cudaFuncSetAttribute(attn_kernel, cudaFuncAttributeMaxDynamicSharedMemorySize, ATTN_SMEM);

    posenc_kernel<<<(TOK*DIM + 255) / 256, 256>>>(features, x);

    dim3 gD(DIM/128, TOK/128);                 // (4,64)
    dim3 gF((FF + 127) / 128, TOK/128);        // (2,64)
    dim3 gA(SEQ/128, NH, NB);                  // (16,8,4)

    for (int l = 0; l < NL; l++) {
        gemm128_kernel<0><<<gD, 256>>>(x, Wq + (size_t)l*DIM*DIM, bq + l*DIM, q, TOK, DIM, DIM);
        gemm128_kernel<0><<<gD, 256>>>(x, Wk + (size_t)l*DIM*DIM, bk + l*DIM, k, TOK, DIM, DIM);
        gemm128_kernel<0><<<gD, 256>>>(x, Wv + (size_t)l*DIM*DIM, bv + l*DIM, v, TOK, DIM, DIM);
        attn_kernel<<<gA, 256, ATTN_SMEM>>>(q, k, v, y);
        gemm128_kernel<0><<<gD, 256>>>(y, Wo + (size_t)l*DIM*DIM, bo + l*DIM, t, TOK, DIM, DIM);
        ln_kernel<<<TOK, 128>>>(x, t, ln1w + l*DIM, ln1b + l*DIM, x);
        gemm128_kernel<1><<<gF, 256>>>(x, W1 + (size_t)l*DIM*FF, b1 + l*FF, hbuf, TOK, DIM, FF);
        gemm128_kernel<0><<<gD, 256>>>(hbuf, W2 + (size_t)l*FF*DIM, b2 + l*DIM, t, TOK, FF, DIM);
        float* lnout = (l == NL-1) ? out : x;
        ln_kernel<<<TOK, 128>>>(x, t, ln2w + l*DIM, ln2b + l*DIM, lnout);
    }
}

// round 4
// speedup vs baseline: 1.2292x; 1.2292x over previous
#include <cuda_runtime.h>

#define TOK 8192
#define SEQ 2048
#define DIM 512
#define NH  8
#define HDM 64
#define NL  4
#define FF  200
#define NB  4

// ---------------- device scratch (allocation-free) ----------------
__device__ float g_x[TOK*DIM];
__device__ float g_q[TOK*DIM];
__device__ float g_k[TOK*DIM];
__device__ float g_v[TOK*DIM];
__device__ float g_y[TOK*DIM];
__device__ float g_t[TOK*DIM];
__device__ float g_h[TOK*FF];

// ---------------- fast exp2 on the FMA pipe (input <= 0) ----------------
__device__ __forceinline__ float exp2_fast(float t) {
    t = fmaxf(t, -126.0f);
    float z = t + 12582912.0f;
    int   ii = __float_as_int(z);
    float n  = z - 12582912.0f;
    float f  = t - n;
    float p  =            1.535336188319500e-4f;
    p = fmaf(p, f, 1.339887440266574e-3f);
    p = fmaf(p, f, 9.618437357674640e-3f);
    p = fmaf(p, f, 5.550332471162809e-2f);
    p = fmaf(p, f, 2.402264791363012e-1f);
    p = fmaf(p, f, 6.931472028550421e-1f);
    p = fmaf(p, f, 1.0f);
    return __int_as_float(__float_as_int(p) + (ii << 23));
}

// ---------------- positional encoding ----------------
__global__ void posenc_kernel(const float* __restrict__ f, float* __restrict__ x) {
    int idx = blockIdx.x * blockDim.x + threadIdx.x;
    if (idx >= TOK*DIM) return;
    int d = idx & (DIM-1);
    int s = (idx / DIM) & (SEQ-1);
    int i2 = d & ~1;
    float div = expf((float)i2 * (-9.210340371976184f / (float)DIM));
    float ang = (float)s * div;
    float pe = (d & 1) ? cosf(ang) : sinf(ang);
    x[idx] = f[idx] + pe;
}

// ---------------- SGEMM 128x128x8, double-buffered smem ----------------
template<int RELU>
__global__ __launch_bounds__(256, 2)
void gemm128_kernel(const float* __restrict__ A, const float* __restrict__ B,
                    const float* __restrict__ bias, float* __restrict__ C,
                    int M, int K, int Nn) {
    __shared__ float As[2][8][128];   // A^T tile, two stages
    __shared__ float Bs[2][8][128];
    int tid = threadIdx.x;
    int tx = tid & 15, ty = tid >> 4;
    int m0 = blockIdx.y * 128, n0 = blockIdx.x * 128;

    int a_row = tid >> 1;                // 0..127
    int a_kg  = (tid & 1) * 4;           // 0 or 4
    int b_k   = tid >> 5;                // 0..7
    int b_col = (tid & 31) * 4;          // 0..124
    int gn_ld = n0 + b_col;

    float acc[8][8] = {};

    // helper lambdas as macros (keep everything inlined)
    const float* aPtr = &A[(size_t)(m0 + a_row) * K + a_kg];
    const float* bPtr = &B[(size_t)b_k * Nn];

    // preload stage 0
    float4 av = *(const float4*)(aPtr + 0);
    float4 bv;
    if (gn_ld + 3 < Nn) {
        bv = *(const float4*)(bPtr + gn_ld);
    } else {
        bv.x = (gn_ld + 0 < Nn) ? bPtr[gn_ld + 0] : 0.f;
        bv.y = (gn_ld + 1 < Nn) ? bPtr[gn_ld + 1] : 0.f;
        bv.z = (gn_ld + 2 < Nn) ? bPtr[gn_ld + 2] : 0.f;
        bv.w = (gn_ld + 3 < Nn) ? bPtr[gn_ld + 3] : 0.f;
    }
    As[0][a_kg + 0][a_row] = av.x;
    As[0][a_kg + 1][a_row] = av.y;
    As[0][a_kg + 2][a_row] = av.z;
    As[0][a_kg + 3][a_row] = av.w;
    *(float4*)&Bs[0][b_k][b_col] = bv;
    __syncthreads();

    int buf = 0;
    for (int k0 = 0; k0 < K; k0 += 8) {
        bool more = (k0 + 8 < K);
        float4 av2, bv2;
        if (more) {
            av2 = *(const float4*)(aPtr + k0 + 8);
            const float* br = bPtr + (size_t)(k0 + 8) * Nn;
            if (gn_ld + 3 < Nn) {
                bv2 = *(const float4*)(br + gn_ld);
            } else {
                bv2.x = (gn_ld + 0 < Nn) ? br[gn_ld + 0] : 0.f;
                bv2.y = (gn_ld + 1 < Nn) ? br[gn_ld + 1] : 0.f;
                bv2.z = (gn_ld + 2 < Nn) ? br[gn_ld + 2] : 0.f;
                bv2.w = (gn_ld + 3 < Nn) ? br[gn_ld + 3] : 0.f;
            }
        }

        #pragma unroll
        for (int k = 0; k < 8; k++) {
            float4 a0 = *(const float4*)&As[buf][k][ty * 4];
            float4 a1 = *(const float4*)&As[buf][k][64 + ty * 4];
            float4 b0 = *(const float4*)&Bs[buf][k][tx * 4];
            float4 b1 = *(const float4*)&Bs[buf][k][64 + tx * 4];
            float ar[8] = {a0.x, a0.y, a0.z, a0.w, a1.x, a1.y, a1.z, a1.w};
            float br[8] = {b0.x, b0.y, b0.z, b0.w, b1.x, b1.y, b1.z, b1.w};
            #pragma unroll
            for (int i = 0; i < 8; i++)
                #pragma unroll
                for (int j = 0; j < 8; j++)
                    acc[i][j] = fmaf(ar[i], br[j], acc[i][j]);
        }

        if (more) {
            int nb = buf ^ 1;
            As[nb][a_kg + 0][a_row] = av2.x;
            As[nb][a_kg + 1][a_row] = av2.y;
            As[nb][a_kg + 2][a_row] = av2.z;
            As[nb][a_kg + 3][a_row] = av2.w;
            *(float4*)&Bs[nb][b_k][b_col] = bv2;
        }
        __syncthreads();
        buf ^= 1;
    }

    // epilogue
    #pragma unroll
    for (int i = 0; i < 8; i++) {
        int gm = m0 + ((i < 4) ? (ty * 4 + i) : (64 + ty * 4 + i - 4));
        #pragma unroll
        for (int j = 0; j < 8; j++) {
            int gn = n0 + ((j < 4) ? (tx * 4 + j) : (64 + tx * 4 + j - 4));
            if (gn < Nn) {
                float vv = acc[i][j] + bias[gn];
                if (RELU) vv = fmaxf(vv, 0.f);
                C[(size_t)gm * Nn + gn] = vv;
            }
        }
    }
}

// ---------------- flash attention: BQ=128, BK=64, 8x4 per thread -----------
#define QT_STRIDE 132
#define KT_STRIDE 68
#define ATTN_SMEM ((64*132 + 64*68 + 64*68 + 64*132) * 4)

__global__ __launch_bounds__(256)
void attn_kernel(const float* __restrict__ q, const float* __restrict__ k,
                 const float* __restrict__ v, float* __restrict__ y) {
    extern __shared__ float sm[];
    float* Qt = sm;                          // [d][row]  64 x 132
    float* Kt = Qt + 64 * QT_STRIDE;         // [d][col]  64 x 68
    float* Vs = Kt + 64 * KT_STRIDE;         // [c][d]    64 x 68
    float* Pt = Vs + 64 * KT_STRIDE;         // [c][row]  64 x 132

    int tid = threadIdx.x;
    int tx = tid & 15, ty = tid >> 4;
    int qt_blk = blockIdx.x, h = blockIdx.y, n = blockIdx.z;
    const float SCALE_LOG2E = 0.125f * 1.4426950408889634f;

    int qbase = n * SEQ + qt_blk * 128;
    int hoff = h * HDM;

    #pragma unroll
    for (int it = 0; it < 8; it++) {
        int idx4 = tid + it * 256;
        int row = idx4 >> 4;
        int d = (idx4 & 15) * 4;
        float4 qv = *(const float4*)&q[(size_t)(qbase + row) * DIM + hoff + d];
        Qt[(d + 0) * QT_STRIDE + row] = qv.x;
        Qt[(d + 1) * QT_STRIDE + row] = qv.y;
        Qt[(d + 2) * QT_STRIDE + row] = qv.z;
        Qt[(d + 3) * QT_STRIDE + row] = qv.w;
    }

    float O[8][4] = {};
    float mrow[8];
    float lrow[8] = {};
    #pragma unroll
    for (int i = 0; i < 8; i++) mrow[i] = -1e30f;
    __syncthreads();

    for (int kt = 0; kt < SEQ / 64; kt++) {
        int kbase = n * SEQ + kt * 64;
        #pragma unroll
        for (int it = 0; it < 4; it++) {
            int idx4 = tid + it * 256;
            int r = idx4 >> 4;
            int d = (idx4 & 15) * 4;
            float4 kv = *(const float4*)&k[(size_t)(kbase + r) * DIM + hoff + d];
            Kt[(d + 0) * KT_STRIDE + r] = kv.x;
            Kt[(d + 1) * KT_STRIDE + r] = kv.y;
            Kt[(d + 2) * KT_STRIDE + r] = kv.z;
            Kt[(d + 3) * KT_STRIDE + r] = kv.w;
            float4 vv = *(const float4*)&v[(size_t)(kbase + r) * DIM + hoff + d];
            *(float4*)&Vs[r * KT_STRIDE + d] = vv;
        }
        __syncthreads();

        float s[8][4] = {};
        #pragma unroll
        for (int d = 0; d < 64; d++) {
            float4 a0 = *(const float4*)&Qt[d * QT_STRIDE + ty * 8];
            float4 a1 = *(const float4*)&Qt[d * QT_STRIDE + ty * 8 + 4];
            float4 b  = *(const float4*)&Kt[d * KT_STRIDE + tx * 4];
            float ar[8] = {a0.x, a0.y, a0.z, a0.w, a1.x, a1.y, a1.z, a1.w};
            float br[4] = {b.x, b.y, b.z, b.w};
            #pragma unroll
            for (int i = 0; i < 8; i++)
                #pragma unroll
                for (int j = 0; j < 4; j++)
                    s[i][j] = fmaf(ar[i], br[j], s[i][j]);
        }

        #pragma unroll
        for (int i = 0; i < 8; i++) {
            float t0 = s[i][0] * SCALE_LOG2E;
            float t1 = s[i][1] * SCALE_LOG2E;
            float t2 = s[i][2] * SCALE_LOG2E;
            float t3 = s[i][3] * SCALE_LOG2E;
            float mloc = fmaxf(fmaxf(t0, t1), fmaxf(t2, t3));
            #pragma unroll
            for (int off = 8; off; off >>= 1)
                mloc = fmaxf(mloc, __shfl_xor_sync(0xffffffffu, mloc, off));
            float newm = fmaxf(mrow[i], mloc);
            float corr = exp2_fast(mrow[i] - newm);
            mrow[i] = newm;
            float p0 = exp2_fast(t0 - newm);
            float p1 = exp2_fast(t1 - newm);
            float p2 = exp2_fast(t2 - newm);
            float p3 = exp2_fast(t3 - newm);
            float rs = (p0 + p1) + (p2 + p3);
            #pragma unroll
            for (int off = 8; off; off >>= 1)
                rs += __shfl_xor_sync(0xffffffffu, rs, off);
            lrow[i] = lrow[i] * corr + rs;
            #pragma unroll
            for (int j = 0; j < 4; j++) O[i][j] *= corr;
            s[i][0] = p0; s[i][1] = p1; s[i][2] = p2; s[i][3] = p3;
        }

        #pragma unroll
        for (int j = 0; j < 4; j++) {
            int c = tx * 4 + j;
            float4 p0 = make_float4(s[0][j], s[1][j], s[2][j], s[3][j]);
            float4 p1 = make_float4(s[4][j], s[5][j], s[6][j], s[7][j]);
            *(float4*)&Pt[c * QT_STRIDE + ty * 8] = p0;
            *(float4*)&Pt[c * QT_STRIDE + ty * 8 + 4] = p1;
        }
        __syncthreads();

        #pragma unroll
        for (int c = 0; c < 64; c++) {
            float4 a0 = *(const float4*)&Pt[c * QT_STRIDE + ty * 8];
            float4 a1 = *(const float4*)&Pt[c * QT_STRIDE + ty * 8 + 4];
            float4 b  = *(const float4*)&Vs[c * KT_STRIDE + tx * 4];
            float ar[8] = {a0.x, a0.y, a0.z, a0.w, a1.x, a1.y, a1.z, a1.w};
            float br[4] = {b.x, b.y, b.z, b.w};
            #pragma unroll
            for (int i = 0; i < 8; i++)
                #pragma unroll
                for (int j = 0; j < 4; j++)
                    O[i][j] = fmaf(ar[i], br[j], O[i][j]);
        }
        __syncthreads();
    }

    #pragma unroll
    for (int i = 0; i < 8; i++) {
        float inv = 1.0f / lrow[i];
        int row = qbase + ty * 8 + i;
        float4 ov = make_float4(O[i][0] * inv, O[i][1] * inv, O[i][2] * inv, O[i][3] * inv);
        *(float4*)&y[(size_t)row * DIM + hoff + tx * 4] = ov;
    }
}

// ---------------- fused residual + LayerNorm ----------------
__global__ void ln_kernel(const float* __restrict__ x, const float* __restrict__ r,
                          const float* __restrict__ w, const float* __restrict__ b,
                          float* __restrict__ out) {
    int row = blockIdx.x;
    int tid = threadIdx.x;
    const float* xr = x + (size_t)row * DIM;
    const float* rr = r + (size_t)row * DIM;
    float vals[4];
    float sum = 0.f;
    #pragma unroll
    for (int i = 0; i < 4; i++) {
        int d = tid + i*128;
        vals[i] = xr[d] + rr[d];
        sum += vals[i];
    }
    __shared__ float red1[4], red2[4];
    #pragma unroll
    for (int off = 16; off; off >>= 1) sum += __shfl_xor_sync(0xffffffffu, sum, off);
    if ((tid & 31) == 0) red1[tid >> 5] = sum;
    __syncthreads();
    sum = red1[0] + red1[1] + red1[2] + red1[3];
    float mean = sum * (1.f / DIM);
    float vs = 0.f;
    #pragma unroll
    for (int i = 0; i < 4; i++) {
        float dv = vals[i] - mean;
        vs += dv * dv;
    }
    #pragma unroll
    for (int off = 16; off; off >>= 1) vs += __shfl_xor_sync(0xffffffffu, vs, off);
    if ((tid & 31) == 0) red2[tid >> 5] = vs;
    __syncthreads();
    vs = red2[0] + red2[1] + red2[2] + red2[3];
    float rstd = rsqrtf(vs * (1.f / DIM) + 1e-5f);
    #pragma unroll
    for (int i = 0; i < 4; i++) {
        int d = tid + i*128;
        out[(size_t)row * DIM + d] = (vals[i] - mean) * rstd * w[d] + b[d];
    }
}

// ---------------- host ----------------
extern "C" void kernel_launch(void* const* d_in, const int* in_sizes, int n_in,
                              void* d_out, int out_size) {
    const float* features = (const float*)d_in[0];
    const float* Wq = (const float*)d_in[1];
    const float* bq = (const float*)d_in[2];
    const float* Wk = (const float*)d_in[3];
    const float* bk = (const float*)d_in[4];
    const float* Wv = (const float*)d_in[5];
    const float* bv = (const float*)d_in[6];
    const float* Wo = (const float*)d_in[7];
    const float* bo = (const float*)d_in[8];
    const float* W1 = (const float*)d_in[9];
    const float* b1 = (const float*)d_in[10];
    const float* W2 = (const float*)d_in[11];
    const float* b2 = (const float*)d_in[12];
    const float* ln1w = (const float*)d_in[13];
    const float* ln1b = (const float*)d_in[14];
    const float* ln2w = (const float*)d_in[15];
    const float* ln2b = (const float*)d_in[16];
    float* out = (float*)d_out;

    float *x, *q, *k, *v, *y, *t, *hbuf;
    cudaGetSymbolAddress((void**)&x, g_x);
    cudaGetSymbolAddress((void**)&q, g_q);
    cudaGetSymbolAddress((void**)&k, g_k);
    cudaGetSymbolAddress((void**)&v, g_v);
    cudaGetSymbolAddress((void**)&y, g_y);
    cudaGetSymbolAddress((void**)&t, g_t);
    cudaGetSymbolAddress((void**)&hbuf, g_h);

    cudaFuncSetAttribute(attn_kernel, cudaFuncAttributeMaxDynamicSharedMemorySize, ATTN_SMEM);

    posenc_kernel<<<(TOK*DIM + 255) / 256, 256>>>(features, x);

    dim3 gD(DIM/128, TOK/128);                 // (4,64)
    dim3 gF((FF + 127) / 128, TOK/128);        // (2,64)
    dim3 gA(SEQ/128, NH, NB);                  // (16,8,4)

    for (int l = 0; l < NL; l++) {
        gemm128_kernel<0><<<gD, 256>>>(x, Wq + (size_t)l*DIM*DIM, bq + l*DIM, q, TOK, DIM, DIM);
        gemm128_kernel<0><<<gD, 256>>>(x, Wk + (size_t)l*DIM*DIM, bk + l*DIM, k, TOK, DIM, DIM);
        gemm128_kernel<0><<<gD, 256>>>(x, Wv + (size_t)l*DIM*DIM, bv + l*DIM, v, TOK, DIM, DIM);
        attn_kernel<<<gA, 256, ATTN_SMEM>>>(q, k, v, y);
        gemm128_kernel<0><<<gD, 256>>>(y, Wo + (size_t)l*DIM*DIM, bo + l*DIM, t, TOK, DIM, DIM);
        ln_kernel<<<TOK, 128>>>(x, t, ln1w + l*DIM, ln1b + l*DIM, x);
        gemm128_kernel<1><<<gF, 256>>>(x, W1 + (size_t)l*DIM*FF, b1 + l*FF, hbuf, TOK, DIM, FF);
        gemm128_kernel<0><<<gD, 256>>>(hbuf, W2 + (size_t)l*FF*DIM, b2 + l*DIM, t, TOK, FF, DIM);
        float* lnout = (l == NL-1) ? out : x;
        ln_kernel<<<TOK, 128>>>(x, t, ln2w + l*DIM, ln2b + l*DIM, lnout);
    }
}

// round 5
// speedup vs baseline: 1.2576x; 1.0231x over previous
#include <cuda_runtime.h>

#define TOK 8192
#define SEQ 2048
#define DIM 512
#define NH  8
#define HDM 64
#define NL  4
#define FF  200
#define NB  4

typedef unsigned long long u64t;

// ---------------- device scratch (allocation-free) ----------------
__device__ float g_x[TOK*DIM];
__device__ float g_q[TOK*DIM];
__device__ float g_k[TOK*DIM];
__device__ float g_v[TOK*DIM];
__device__ float g_y[TOK*DIM];
__device__ float g_t[TOK*DIM];
__device__ float g_h[TOK*FF];

// ---------------- packed f32x2 helpers ----------------
__device__ __forceinline__ void fma2(u64t& d, u64t a, u64t b) {
    asm volatile("fma.rn.f32x2 %0, %1, %2, %0;" : "+l"(d) : "l"(a), "l"(b));
}
__device__ __forceinline__ void mul2(u64t& d, u64t a, u64t b) {
    asm volatile("mul.rn.f32x2 %0, %1, %2;" : "=l"(d) : "l"(a), "l"(b));
}
__device__ __forceinline__ void lds2(u64t& a, u64t& b, unsigned addr) {
    asm volatile("ld.shared.v2.b64 {%0,%1}, [%2];" : "=l"(a), "=l"(b) : "r"(addr));
}
__device__ __forceinline__ void unpack2(float& lo, float& hi, u64t p) {
    asm volatile("mov.b64 {%0,%1}, %2;" : "=f"(lo), "=f"(hi) : "l"(p));
}
__device__ __forceinline__ u64t dup2(float v) {
    u64t p;
    asm volatile("mov.b64 %0, {%1,%1};" : "=l"(p) : "f"(v));
    return p;
}
__device__ __forceinline__ u64t pk2(float lo, float hi) {
    u64t p;
    asm volatile("mov.b64 %0, {%1,%2};" : "=l"(p) : "f"(lo), "f"(hi));
    return p;
}
__device__ __forceinline__ unsigned su32(const void* p) {
    return (unsigned)__cvta_generic_to_shared(p);
}

// ---------------- fast exp2 on the FMA pipe (input <= 0) ----------------
__device__ __forceinline__ float exp2_fast(float t) {
    t = fmaxf(t, -126.0f);
    float z = t + 12582912.0f;
    int   ii = __float_as_int(z);
    float n  = z - 12582912.0f;
    float f  = t - n;
    float p  =            1.535336188319500e-4f;
    p = fmaf(p, f, 1.339887440266574e-3f);
    p = fmaf(p, f, 9.618437357674640e-3f);
    p = fmaf(p, f, 5.550332471162809e-2f);
    p = fmaf(p, f, 2.402264791363012e-1f);
    p = fmaf(p, f, 6.931472028550421e-1f);
    p = fmaf(p, f, 1.0f);
    return __int_as_float(__float_as_int(p) + (ii << 23));
}

// ---------------- positional encoding ----------------
__global__ void posenc_kernel(const float* __restrict__ f, float* __restrict__ x) {
    int idx = blockIdx.x * blockDim.x + threadIdx.x;
    if (idx >= TOK*DIM) return;
    int d = idx & (DIM-1);
    int s = (idx / DIM) & (SEQ-1);
    int i2 = d & ~1;
    float div = expf((float)i2 * (-9.210340371976184f / (float)DIM));
    float ang = (float)s * div;
    float pe = (d & 1) ? cosf(ang) : sinf(ang);
    x[idx] = f[idx] + pe;
}

// ---------------- SGEMM 128x128x8, double-buffered, FFMA2 microkernel ------
template<int RELU>
__global__ __launch_bounds__(256, 2)
void gemm128_kernel(const float* __restrict__ A, const float* __restrict__ B,
                    const float* __restrict__ bias, float* __restrict__ C,
                    int M, int K, int Nn) {
    __shared__ float As[2][8][128];   // A^T tile, two stages
    __shared__ float Bs[2][8][128];
    int tid = threadIdx.x;
    int tx = tid & 15, ty = tid >> 4;
    int m0 = blockIdx.y * 128, n0 = blockIdx.x * 128;

    int a_row = tid >> 1;
    int a_kg  = (tid & 1) * 4;
    int b_k   = tid >> 5;
    int b_col = (tid & 31) * 4;
    int gn_ld = n0 + b_col;

    unsigned bBase = su32(&Bs[0][0][0]);

    u64t acc[8][4] = {};   // 8 rows x 4 col-pairs

    const float* aPtr = &A[(size_t)(m0 + a_row) * K + a_kg];
    const float* bPtr = &B[(size_t)b_k * Nn];

    // preload stage 0
    float4 av = *(const float4*)(aPtr + 0);
    float4 bv;
    if (gn_ld + 3 < Nn) {
        bv = *(const float4*)(bPtr + gn_ld);
    } else {
        bv.x = (gn_ld + 0 < Nn) ? bPtr[gn_ld + 0] : 0.f;
        bv.y = (gn_ld + 1 < Nn) ? bPtr[gn_ld + 1] : 0.f;
        bv.z = (gn_ld + 2 < Nn) ? bPtr[gn_ld + 2] : 0.f;
        bv.w = (gn_ld + 3 < Nn) ? bPtr[gn_ld + 3] : 0.f;
    }
    As[0][a_kg + 0][a_row] = av.x;
    As[0][a_kg + 1][a_row] = av.y;
    As[0][a_kg + 2][a_row] = av.z;
    As[0][a_kg + 3][a_row] = av.w;
    *(float4*)&Bs[0][b_k][b_col] = bv;
    __syncthreads();

    int buf = 0;
    for (int k0 = 0; k0 < K; k0 += 8) {
        bool more = (k0 + 8 < K);
        float4 av2, bv2;
        if (more) {
            av2 = *(const float4*)(aPtr + k0 + 8);
            const float* br = bPtr + (size_t)(k0 + 8) * Nn;
            if (gn_ld + 3 < Nn) {
                bv2 = *(const float4*)(br + gn_ld);
            } else {
                bv2.x = (gn_ld + 0 < Nn) ? br[gn_ld + 0] : 0.f;
                bv2.y = (gn_ld + 1 < Nn) ? br[gn_ld + 1] : 0.f;
                bv2.z = (gn_ld + 2 < Nn) ? br[gn_ld + 2] : 0.f;
                bv2.w = (gn_ld + 3 < Nn) ? br[gn_ld + 3] : 0.f;
            }
        }

        unsigned bufOff = (unsigned)buf * (8u * 128u * 4u);
        #pragma unroll
        for (int k = 0; k < 8; k++) {
            float4 a0 = *(const float4*)&As[buf][k][ty * 4];
            float4 a1 = *(const float4*)&As[buf][k][64 + ty * 4];
            u64t bp[4];
            unsigned baddr = bBase + bufOff + (unsigned)(k * 128 + tx * 4) * 4u;
            lds2(bp[0], bp[1], baddr);
            lds2(bp[2], bp[3], baddr + 256u);     // +64 cols
            u64t ad[8];
            ad[0] = dup2(a0.x); ad[1] = dup2(a0.y);
            ad[2] = dup2(a0.z); ad[3] = dup2(a0.w);
            ad[4] = dup2(a1.x); ad[5] = dup2(a1.y);
            ad[6] = dup2(a1.z); ad[7] = dup2(a1.w);
            #pragma unroll
            for (int i = 0; i < 8; i++)
                #pragma unroll
                for (int jp = 0; jp < 4; jp++)
                    fma2(acc[i][jp], ad[i], bp[jp]);
        }

        if (more) {
            int nb = buf ^ 1;
            As[nb][a_kg + 0][a_row] = av2.x;
            As[nb][a_kg + 1][a_row] = av2.y;
            As[nb][a_kg + 2][a_row] = av2.z;
            As[nb][a_kg + 3][a_row] = av2.w;
            *(float4*)&Bs[nb][b_k][b_col] = bv2;
        }
        __syncthreads();
        buf ^= 1;
    }

    // epilogue
    #pragma unroll
    for (int i = 0; i < 8; i++) {
        int gm = m0 + ((i < 4) ? (ty * 4 + i) : (64 + ty * 4 + i - 4));
        #pragma unroll
        for (int jp = 0; jp < 4; jp++) {
            float lo, hi;
            unpack2(lo, hi, acc[i][jp]);
            int jbase = (jp < 2) ? (tx * 4 + jp * 2) : (64 + tx * 4 + (jp - 2) * 2);
            int gn0 = n0 + jbase, gn1 = gn0 + 1;
            if (gn0 < Nn) {
                float vv = lo + bias[gn0];
                if (RELU) vv = fmaxf(vv, 0.f);
                C[(size_t)gm * Nn + gn0] = vv;
            }
            if (gn1 < Nn) {
                float vv = hi + bias[gn1];
                if (RELU) vv = fmaxf(vv, 0.f);
                C[(size_t)gm * Nn + gn1] = vv;
            }
        }
    }
}

// ---------------- flash attention: BQ=128, BK=64, FFMA2 microkernels -------
#define QT_STRIDE 132
#define KT_STRIDE 68
#define ATTN_SMEM ((64*132 + 64*68 + 64*68 + 64*132) * 4)

__global__ __launch_bounds__(256)
void attn_kernel(const float* __restrict__ q, const float* __restrict__ k,
                 const float* __restrict__ v, float* __restrict__ y) {
    extern __shared__ float sm[];
    float* Qt = sm;                          // [d][row]  64 x 132
    float* Kt = Qt + 64 * QT_STRIDE;         // [d][col]  64 x 68
    float* Vs = Kt + 64 * KT_STRIDE;         // [c][d]    64 x 68
    float* Pt = Vs + 64 * KT_STRIDE;         // [c][row]  64 x 132

    unsigned kBase = su32(Kt);
    unsigned vBase = su32(Vs);

    int tid = threadIdx.x;
    int tx = tid & 15, ty = tid >> 4;
    int qt_blk = blockIdx.x, h = blockIdx.y, n = blockIdx.z;
    const float SCALE_LOG2E = 0.125f * 1.4426950408889634f;

    int qbase = n * SEQ + qt_blk * 128;
    int hoff = h * HDM;

    #pragma unroll
    for (int it = 0; it < 8; it++) {
        int idx4 = tid + it * 256;
        int row = idx4 >> 4;
        int d = (idx4 & 15) * 4;
        float4 qv = *(const float4*)&q[(size_t)(qbase + row) * DIM + hoff + d];
        Qt[(d + 0) * QT_STRIDE + row] = qv.x;
        Qt[(d + 1) * QT_STRIDE + row] = qv.y;
        Qt[(d + 2) * QT_STRIDE + row] = qv.z;
        Qt[(d + 3) * QT_STRIDE + row] = qv.w;
    }

    u64t O[8][2] = {};
    float mrow[8];
    float lrow[8] = {};
    #pragma unroll
    for (int i = 0; i < 8; i++) mrow[i] = -1e30f;
    __syncthreads();

    for (int kt = 0; kt < SEQ / 64; kt++) {
        int kbase = n * SEQ + kt * 64;
        #pragma unroll
        for (int it = 0; it < 4; it++) {
            int idx4 = tid + it * 256;
            int r = idx4 >> 4;
            int d = (idx4 & 15) * 4;
            float4 kv = *(const float4*)&k[(size_t)(kbase + r) * DIM + hoff + d];
            Kt[(d + 0) * KT_STRIDE + r] = kv.x;
            Kt[(d + 1) * KT_STRIDE + r] = kv.y;
            Kt[(d + 2) * KT_STRIDE + r] = kv.z;
            Kt[(d + 3) * KT_STRIDE + r] = kv.w;
            float4 vv = *(const float4*)&v[(size_t)(kbase + r) * DIM + hoff + d];
            *(float4*)&Vs[r * KT_STRIDE + d] = vv;
        }
        __syncthreads();

        // S = Q K^T  (packed over col pairs)
        u64t s_p[8][2] = {};
        #pragma unroll 8
        for (int d = 0; d < 64; d++) {
            float4 a0 = *(const float4*)&Qt[d * QT_STRIDE + ty * 8];
            float4 a1 = *(const float4*)&Qt[d * QT_STRIDE + ty * 8 + 4];
            u64t bp[2];
            lds2(bp[0], bp[1], kBase + (unsigned)(d * KT_STRIDE + tx * 4) * 4u);
            u64t ad[8];
            ad[0] = dup2(a0.x); ad[1] = dup2(a0.y);
            ad[2] = dup2(a0.z); ad[3] = dup2(a0.w);
            ad[4] = dup2(a1.x); ad[5] = dup2(a1.y);
            ad[6] = dup2(a1.z); ad[7] = dup2(a1.w);
            #pragma unroll
            for (int i = 0; i < 8; i++) {
                fma2(s_p[i][0], ad[i], bp[0]);
                fma2(s_p[i][1], ad[i], bp[1]);
            }
        }

        // online softmax (base-2)
        float ps[8][4];
        #pragma unroll
        for (int i = 0; i < 8; i++) {
            float t0, t1, t2, t3;
            unpack2(t0, t1, s_p[i][0]);
            unpack2(t2, t3, s_p[i][1]);
            t0 *= SCALE_LOG2E; t1 *= SCALE_LOG2E; t2 *= SCALE_LOG2E; t3 *= SCALE_LOG2E;
            float mloc = fmaxf(fmaxf(t0, t1), fmaxf(t2, t3));
            #pragma unroll
            for (int off = 8; off; off >>= 1)
                mloc = fmaxf(mloc, __shfl_xor_sync(0xffffffffu, mloc, off));
            float newm = fmaxf(mrow[i], mloc);
            float corr = exp2_fast(mrow[i] - newm);
            mrow[i] = newm;
            float p0 = exp2_fast(t0 - newm);
            float p1 = exp2_fast(t1 - newm);
            float p2 = exp2_fast(t2 - newm);
            float p3 = exp2_fast(t3 - newm);
            float rs = (p0 + p1) + (p2 + p3);
            #pragma unroll
            for (int off = 8; off; off >>= 1)
                rs += __shfl_xor_sync(0xffffffffu, rs, off);
            lrow[i] = lrow[i] * corr + rs;
            u64t corrp = dup2(corr);
            mul2(O[i][0], O[i][0], corrp);
            mul2(O[i][1], O[i][1], corrp);
            ps[i][0] = p0; ps[i][1] = p1; ps[i][2] = p2; ps[i][3] = p3;
        }

        // store P transposed: Pt[c][row]
        #pragma unroll
        for (int j = 0; j < 4; j++) {
            int c = tx * 4 + j;
            float4 p0 = make_float4(ps[0][j], ps[1][j], ps[2][j], ps[3][j]);
            float4 p1 = make_float4(ps[4][j], ps[5][j], ps[6][j], ps[7][j]);
            *(float4*)&Pt[c * QT_STRIDE + ty * 8] = p0;
            *(float4*)&Pt[c * QT_STRIDE + ty * 8 + 4] = p1;
        }
        __syncthreads();

        // O += P V
        #pragma unroll 8
        for (int c = 0; c < 64; c++) {
            float4 a0 = *(const float4*)&Pt[c * QT_STRIDE + ty * 8];
            float4 a1 = *(const float4*)&Pt[c * QT_STRIDE + ty * 8 + 4];
            u64t bp[2];
            lds2(bp[0], bp[1], vBase + (unsigned)(c * KT_STRIDE + tx * 4) * 4u);
            u64t ad[8];
            ad[0] = dup2(a0.x); ad[1] = dup2(a0.y);
            ad[2] = dup2(a0.z); ad[3] = dup2(a0.w);
            ad[4] = dup2(a1.x); ad[5] = dup2(a1.y);
            ad[6] = dup2(a1.z); ad[7] = dup2(a1.w);
            #pragma unroll
            for (int i = 0; i < 8; i++) {
                fma2(O[i][0], ad[i], bp[0]);
                fma2(O[i][1], ad[i], bp[1]);
            }
        }
        __syncthreads();
    }

    #pragma unroll
    for (int i = 0; i < 8; i++) {
        float inv = 1.0f / lrow[i];
        float o0, o1, o2, o3;
        unpack2(o0, o1, O[i][0]);
        unpack2(o2, o3, O[i][1]);
        int row = qbase + ty * 8 + i;
        float4 ov = make_float4(o0 * inv, o1 * inv, o2 * inv, o3 * inv);
        *(float4*)&y[(size_t)row * DIM + hoff + tx * 4] = ov;
    }
}

// ---------------- fused residual + LayerNorm ----------------
__global__ void ln_kernel(const float* __restrict__ x, const float* __restrict__ r,
                          const float* __restrict__ w, const float* __restrict__ b,
                          float* __restrict__ out) {
    int row = blockIdx.x;
    int tid = threadIdx.x;
    const float* xr = x + (size_t)row * DIM;
    const float* rr = r + (size_t)row * DIM;
    float vals[4];
    float sum = 0.f;
    #pragma unroll
    for (int i = 0; i < 4; i++) {
        int d = tid + i*128;
        vals[i] = xr[d] + rr[d];
        sum += vals[i];
    }
    __shared__ float red1[4], red2[4];
    #pragma unroll
    for (int off = 16; off; off >>= 1) sum += __shfl_xor_sync(0xffffffffu, sum, off);
    if ((tid & 31) == 0) red1[tid >> 5] = sum;
    __syncthreads();
    sum = red1[0] + red1[1] + red1[2] + red1[3];
    float mean = sum * (1.f / DIM);
    float vs = 0.f;
    #pragma unroll
    for (int i = 0; i < 4; i++) {
        float dv = vals[i] - mean;
        vs += dv * dv;
    }
    #pragma unroll
    for (int off = 16; off; off >>= 1) vs += __shfl_xor_sync(0xffffffffu, vs, off);
    if ((tid & 31) == 0) red2[tid >> 5] = vs;
    __syncthreads();
    vs = red2[0] + red2[1] + red2[2] + red2[3];
    float rstd = rsqrtf(vs * (1.f / DIM) + 1e-5f);
    #pragma unroll
    for (int i = 0; i < 4; i++) {
        int d = tid + i*128;
        out[(size_t)row * DIM + d] = (vals[i] - mean) * rstd * w[d] + b[d];
    }
}

// ---------------- host ----------------
extern "C" void kernel_launch(void* const* d_in, const int* in_sizes, int n_in,
                              void* d_out, int out_size) {
    const float* features = (const float*)d_in[0];
    const float* Wq = (const float*)d_in[1];
    const float* bq = (const float*)d_in[2];
    const float* Wk = (const float*)d_in[3];
    const float* bk = (const float*)d_in[4];
    const float* Wv = (const float*)d_in[5];
    const float* bv = (const float*)d_in[6];
    const float* Wo = (const float*)d_in[7];
    const float* bo = (const float*)d_in[8];
    const float* W1 = (const float*)d_in[9];
    const float* b1 = (const float*)d_in[10];
    const float* W2 = (const float*)d_in[11];
    const float* b2 = (const float*)d_in[12];
    const float* ln1w = (const float*)d_in[13];
    const float* ln1b = (const float*)d_in[14];
    const float* ln2w = (const float*)d_in[15];
    const float* ln2b = (const float*)d_in[16];
    float* out = (float*)d_out;

    float *x, *q, *k, *v, *y, *t, *hbuf;
    cudaGetSymbolAddress((void**)&x, g_x);
    cudaGetSymbolAddress((void**)&q, g_q);
    cudaGetSymbolAddress((void**)&k, g_k);
    cudaGetSymbolAddress((void**)&v, g_v);
    cudaGetSymbolAddress((void**)&y, g_y);
    cudaGetSymbolAddress((void**)&t, g_t);
    cudaGetSymbolAddress((void**)&hbuf, g_h);

    cudaFuncSetAttribute(attn_kernel, cudaFuncAttributeMaxDynamicSharedMemorySize, ATTN_SMEM);

    posenc_kernel<<<(TOK*DIM + 255) / 256, 256>>>(features, x);

    dim3 gD(DIM/128, TOK/128);                 // (4,64)
    dim3 gF((FF + 127) / 128, TOK/128);        // (2,64)
    dim3 gA(SEQ/128, NH, NB);                  // (16,8,4)

    for (int l = 0; l < NL; l++) {
        gemm128_kernel<0><<<gD, 256>>>(x, Wq + (size_t)l*DIM*DIM, bq + l*DIM, q, TOK, DIM, DIM);
        gemm128_kernel<0><<<gD, 256>>>(x, Wk + (size_t)l*DIM*DIM, bk + l*DIM, k, TOK, DIM, DIM);
        gemm128_kernel<0><<<gD, 256>>>(x, Wv + (size_t)l*DIM*DIM, bv + l*DIM, v, TOK, DIM, DIM);
        attn_kernel<<<gA, 256, ATTN_SMEM>>>(q, k, v, y);
        gemm128_kernel<0><<<gD, 256>>>(y, Wo + (size_t)l*DIM*DIM, bo + l*DIM, t, TOK, DIM, DIM);
        ln_kernel<<<TOK, 128>>>(x, t, ln1w + l*DIM, ln1b + l*DIM, x);
        gemm128_kernel<1><<<gF, 256>>>(x, W1 + (size_t)l*DIM*FF, b1 + l*FF, hbuf, TOK, DIM, FF);
        gemm128_kernel<0><<<gD, 256>>>(hbuf, W2 + (size_t)l*FF*DIM, b2 + l*DIM, t, TOK, FF, DIM);
        float* lnout = (l == NL-1) ? out : x;
        ln_kernel<<<TOK, 128>>>(x, t, ln2w + l*DIM, ln2b + l*DIM, lnout);
    }
}

// round 7
// speedup vs baseline: 1.5008x; 1.1934x over previous
#include <cuda_runtime.h>
#include <cuda_bf16.h>
#include <cstdint>

#define TOK 8192
#define SEQ 2048
#define DIM 512
#define NH  8
#define HDM 64
#define NL  4
#define FF  200
#define NB  4
#define FFP 256
typedef unsigned long long u64t;

// ---------------- device scratch (allocation-free) ----------------
__device__ float g_x[TOK*DIM];
__device__ float g_q[TOK*DIM];
__device__ float g_k[TOK*DIM];
__device__ float g_v[TOK*DIM];
__device__ float g_y[TOK*DIM];
__device__ float g_t[TOK*DIM];
__device__ float g_h[TOK*FF];
__device__ __nv_bfloat16 g_xh[TOK*DIM];
__device__ __nv_bfloat16 g_xl[TOK*DIM];
__device__ __nv_bfloat16 g_hh[TOK*FFP];
__device__ __nv_bfloat16 g_hl[TOK*FFP];
#define LWSZ 1310720
__device__ __nv_bfloat16 g_wh[4*LWSZ];
__device__ __nv_bfloat16 g_wl[4*LWSZ];

// ---------------- helpers ----------------
__device__ __forceinline__ unsigned su32(const void* p) {
    return (unsigned)__cvta_generic_to_shared(p);
}
__device__ __forceinline__ void fma2(u64t& d, u64t a, u64t b) {
    asm volatile("fma.rn.f32x2 %0, %1, %2, %0;" : "+l"(d) : "l"(a), "l"(b));
}
__device__ __forceinline__ void mul2(u64t& d, u64t a, u64t b) {
    asm volatile("mul.rn.f32x2 %0, %1, %2;" : "=l"(d) : "l"(a), "l"(b));
}
__device__ __forceinline__ void lds2(u64t& a, u64t& b, unsigned addr) {
    asm volatile("ld.shared.v2.b64 {%0,%1}, [%2];" : "=l"(a), "=l"(b) : "r"(addr));
}
__device__ __forceinline__ void unpack2(float& lo, float& hi, u64t p) {
    asm volatile("mov.b64 {%0,%1}, %2;" : "=f"(lo), "=f"(hi) : "l"(p));
}
__device__ __forceinline__ u64t dup2(float v) {
    u64t p;
    asm volatile("mov.b64 %0, {%1,%1};" : "=l"(p) : "f"(v));
    return p;
}
__device__ __forceinline__ void ldsm4(uint32_t* r, unsigned addr) {
    asm volatile("ldmatrix.sync.aligned.m8n8.x4.shared.b16 {%0,%1,%2,%3}, [%4];"
        : "=r"(r[0]), "=r"(r[1]), "=r"(r[2]), "=r"(r[3]) : "r"(addr));
}
__device__ __forceinline__ void ldsm2(uint32_t* r, unsigned addr) {
    asm volatile("ldmatrix.sync.aligned.m8n8.x2.shared.b16 {%0,%1}, [%2];"
        : "=r"(r[0]), "=r"(r[1]) : "r"(addr));
}
__device__ __forceinline__ void mma16816(float* c, const uint32_t* a, const uint32_t* b) {
    asm volatile("mma.sync.aligned.m16n8k16.row.col.f32.bf16.bf16.f32 "
        "{%0,%1,%2,%3}, {%4,%5,%6,%7}, {%8,%9}, {%0,%1,%2,%3};"
        : "+f"(c[0]), "+f"(c[1]), "+f"(c[2]), "+f"(c[3])
        : "r"(a[0]), "r"(a[1]), "r"(a[2]), "r"(a[3]), "r"(b[0]), "r"(b[1]));
}

// ---------------- fast exp2 on the FMA pipe (input <= 0) ----------------
__device__ __forceinline__ float exp2_fast(float t) {
    t = fmaxf(t, -126.0f);
    float z = t + 12582912.0f;
    int   ii = __float_as_int(z);
    float n  = z - 12582912.0f;
    float f  = t - n;
    float p  =            1.535336188319500e-4f;
    p = fmaf(p, f, 1.339887440266574e-3f);
    p = fmaf(p, f, 9.618437357674640e-3f);
    p = fmaf(p, f, 5.550332471162809e-2f);
    p = fmaf(p, f, 2.402264791363012e-1f);
    p = fmaf(p, f, 6.931472028550421e-1f);
    p = fmaf(p, f, 1.0f);
    return __int_as_float(__float_as_int(p) + (ii << 23));
}

// ---------------- positional encoding ----------------
__global__ void posenc_kernel(const float* __restrict__ f, float* __restrict__ x) {
    int idx = blockIdx.x * blockDim.x + threadIdx.x;
    if (idx >= TOK*DIM) return;
    int d = idx & (DIM-1);
    int s = (idx / DIM) & (SEQ-1);
    int i2 = d & ~1;
    float div = expf((float)i2 * (-9.210340371976184f / (float)DIM));
    float ang = (float)s * div;
    float pe = (d & 1) ? cosf(ang) : sinf(ang);
    x[idx] = f[idx] + pe;
}

// ---------------- split fp32 -> bf16 hi/lo ----------------
__global__ void split_kernel(const float* __restrict__ x,
                             __nv_bfloat16* __restrict__ h, __nv_bfloat16* __restrict__ l, int n) {
    int idx = blockIdx.x * blockDim.x + threadIdx.x;
    if (idx >= n) return;
    float v = x[idx];
    __nv_bfloat16 hb = __float2bfloat16(v);
    h[idx] = hb;
    l[idx] = __float2bfloat16(v - __bfloat162float(hb));
}
__global__ void split_pad_kernel(const float* __restrict__ x,
                                 __nv_bfloat16* __restrict__ h, __nv_bfloat16* __restrict__ l) {
    int idx = blockIdx.x * blockDim.x + threadIdx.x;
    if (idx >= TOK*FFP) return;
    int r = idx >> 8, c = idx & 255;
    float v = (c < FF) ? x[r*FF + c] : 0.f;
    __nv_bfloat16 hb = __float2bfloat16(v);
    h[idx] = hb;
    l[idx] = __float2bfloat16(v - __bfloat162float(hb));
}
// W [Kreal,Nreal] -> [Npad][Kpad] hi/lo, zero-padded
__global__ void transpose_split_kernel(const float* __restrict__ W,
                                       int Kreal, int Nreal, int Kpad, int Npad,
                                       __nv_bfloat16* __restrict__ oh, __nv_bfloat16* __restrict__ ol) {
    int idx = blockIdx.x * blockDim.x + threadIdx.x;
    if (idx >= Npad * Kpad) return;
    int n = idx % Npad, k = idx / Npad;
    float v = (n < Nreal && k < Kreal) ? W[(size_t)k * Nreal + n] : 0.f;
    __nv_bfloat16 hb = __float2bfloat16(v);
    oh[(size_t)n * Kpad + k] = hb;
    ol[(size_t)n * Kpad + k] = __float2bfloat16(v - __bfloat162float(hb));
}

// ---------------- bf16-split GEMM via mma.sync (HMMA) ----------------
// C[M,Nn] = A[M,KTOT] @ B^T (B stored [Npad][KTOT]), fp32 accumulate.
// 256 threads, tile M=128 x N=128. Warps 4x2; each warp 32 rows x 64 cols.
#define AST_B 144                       // smem row stride bytes (64 bf16 + 8 pad)
#define TILE_B (128 * AST_B)            // 18432
#define GEMM_SMEM (4 * TILE_B)          // 73728

template<int KTOT, int RELU>
__global__ __launch_bounds__(256, 2)
void mma_gemm(const __nv_bfloat16* __restrict__ Ah, const __nv_bfloat16* __restrict__ Al,
              const __nv_bfloat16* __restrict__ Bh, const __nv_bfloat16* __restrict__ Bl,
              const float* __restrict__ bias, float* __restrict__ C, int Nn) {
    extern __shared__ char smem[];
    char* pAh = smem;
    char* pAl = smem + TILE_B;
    char* pBh = smem + 2*TILE_B;
    char* pBl = smem + 3*TILE_B;
    unsigned sAh = su32(pAh), sAl = su32(pAl), sBh = su32(pBh), sBl = su32(pBl);

    int tid = threadIdx.x;
    int wid = tid >> 5, lane = tid & 31;
    int warp_m = wid & 3, warp_n = wid >> 2;
    int m0 = blockIdx.y * 128, n0 = blockIdx.x * 128;

    float acc[2][8][4] = {};

    for (int k0 = 0; k0 < KTOT; k0 += 64) {
        // load 4 tiles of [128 rows][64 bf16] (128 bytes/row)
        #pragma unroll
        for (int it = 0; it < 4; it++) {
            int chunk = tid + it * 256;          // 0..1023
            int r = chunk >> 3;
            int cb = (chunk & 7) * 16;           // byte col
            size_t ga = ((size_t)(m0 + r) * KTOT + k0) * 2 + cb;
            size_t gb = ((size_t)(n0 + r) * KTOT + k0) * 2 + cb;
            unsigned so = (unsigned)(r * AST_B + cb);
            *(uint4*)(pAh + so) = *(const uint4*)((const char*)Ah + ga);
            *(uint4*)(pAl + so) = *(const uint4*)((const char*)Al + ga);
            *(uint4*)(pBh + so) = *(const uint4*)((const char*)Bh + gb);
            *(uint4*)(pBl + so) = *(const uint4*)((const char*)Bl + gb);
        }
        __syncthreads();

        #pragma unroll
        for (int ks = 0; ks < 4; ks++) {
            int colb = ks * 32;                  // 16 bf16 per k-step
            uint32_t ah[2][4], al[2][4];
            #pragma unroll
            for (int mt = 0; mt < 2; mt++) {
                unsigned ra = (unsigned)((warp_m*32 + mt*16 + (lane & 15)) * AST_B
                                          + colb + (lane >> 4) * 16);
                ldsm4(ah[mt], sAh + ra);
                ldsm4(al[mt], sAl + ra);
            }
            #pragma unroll
            for (int nt = 0; nt < 8; nt++) {
                unsigned rb = (unsigned)((warp_n*64 + nt*8 + (lane & 7)) * AST_B
                                          + colb + ((lane >> 3) & 1) * 16);
                uint32_t bh[2], bl[2];
                ldsm2(bh, sBh + rb);
                ldsm2(bl, sBl + rb);
                #pragma unroll
                for (int mt = 0; mt < 2; mt++) {
                    mma16816(acc[mt][nt], ah[mt], bh);
                    mma16816(acc[mt][nt], ah[mt], bl);
                    mma16816(acc[mt][nt], al[mt], bh);
                }
            }
        }
        __syncthreads();
    }

    // epilogue: direct stores (c-fragment layout)
    #pragma unroll
    for (int mt = 0; mt < 2; mt++) {
        int r0 = m0 + warp_m*32 + mt*16 + (lane >> 2);
        #pragma unroll
        for (int nt = 0; nt < 8; nt++) {
            int c0 = n0 + warp_n*64 + nt*8 + 2*(lane & 3);
            if (c0 < Nn) {
                float2 bb = *(const float2*)&bias[c0];
                float v0 = acc[mt][nt][0] + bb.x;
                float v1 = acc[mt][nt][1] + bb.y;
                float v2 = acc[mt][nt][2] + bb.x;
                float v3 = acc[mt][nt][3] + bb.y;
                if (RELU) {
                    v0 = fmaxf(v0, 0.f); v1 = fmaxf(v1, 0.f);
                    v2 = fmaxf(v2, 0.f); v3 = fmaxf(v3, 0.f);
                }
                *(float2*)&C[(size_t)r0 * Nn + c0] = make_float2(v0, v1);
                *(float2*)&C[(size_t)(r0 + 8) * Nn + c0] = make_float2(v2, v3);
            }
        }
    }
}

// ---------------- flash attention: BQ=128, BK=64, FFMA2 microkernels -------
#define QT_STRIDE 132
#define KT_STRIDE 68
#define ATTN_SMEM ((64*132 + 64*68 + 64*68 + 64*132) * 4)

__global__ __launch_bounds__(256)
void attn_kernel(const float* __restrict__ q, const float* __restrict__ k,
                 const float* __restrict__ v, float* __restrict__ y) {
    extern __shared__ float sm[];
    float* Qt = sm;
    float* Kt = Qt + 64 * QT_STRIDE;
    float* Vs = Kt + 64 * KT_STRIDE;
    float* Pt = Vs + 64 * KT_STRIDE;

    unsigned kBase = su32(Kt);
    unsigned vBase = su32(Vs);

    int tid = threadIdx.x;
    int tx = tid & 15, ty = tid >> 4;
    int qt_blk = blockIdx.x, h = blockIdx.y, n = blockIdx.z;
    const float SCALE_LOG2E = 0.125f * 1.4426950408889634f;

    int qbase = n * SEQ + qt_blk * 128;
    int hoff = h * HDM;

    #pragma unroll
    for (int it = 0; it < 8; it++) {
        int idx4 = tid + it * 256;
        int row = idx4 >> 4;
        int d = (idx4 & 15) * 4;
        float4 qv = *(const float4*)&q[(size_t)(qbase + row) * DIM + hoff + d];
        Qt[(d + 0) * QT_STRIDE + row] = qv.x;
        Qt[(d + 1) * QT_STRIDE + row] = qv.y;
        Qt[(d + 2) * QT_STRIDE + row] = qv.z;
        Qt[(d + 3) * QT_STRIDE + row] = qv.w;
    }

    u64t O[8][2] = {};
    float mrow[8];
    float lrow[8] = {};
    #pragma unroll
    for (int i = 0; i < 8; i++) mrow[i] = -1e30f;
    __syncthreads();

    for (int kt = 0; kt < SEQ / 64; kt++) {
        int kbase = n * SEQ + kt * 64;
        #pragma unroll
        for (int it = 0; it < 4; it++) {
            int idx4 = tid + it * 256;
            int r = idx4 >> 4;
            int d = (idx4 & 15) * 4;
            float4 kv = *(const float4*)&k[(size_t)(kbase + r) * DIM + hoff + d];
            Kt[(d + 0) * KT_STRIDE + r] = kv.x;
            Kt[(d + 1) * KT_STRIDE + r] = kv.y;
            Kt[(d + 2) * KT_STRIDE + r] = kv.z;
            Kt[(d + 3) * KT_STRIDE + r] = kv.w;
            float4 vv = *(const float4*)&v[(size_t)(kbase + r) * DIM + hoff + d];
            *(float4*)&Vs[r * KT_STRIDE + d] = vv;
        }
        __syncthreads();

        u64t s_p[8][2] = {};
        #pragma unroll 8
        for (int d = 0; d < 64; d++) {
            float4 a0 = *(const float4*)&Qt[d * QT_STRIDE + ty * 8];
            float4 a1 = *(const float4*)&Qt[d * QT_STRIDE + ty * 8 + 4];
            u64t bp[2];
            lds2(bp[0], bp[1], kBase + (unsigned)(d * KT_STRIDE + tx * 4) * 4u);
            u64t ad[8];
            ad[0] = dup2(a0.x); ad[1] = dup2(a0.y);
            ad[2] = dup2(a0.z); ad[3] = dup2(a0.w);
            ad[4] = dup2(a1.x); ad[5] = dup2(a1.y);
            ad[6] = dup2(a1.z); ad[7] = dup2(a1.w);
            #pragma unroll
            for (int i = 0; i < 8; i++) {
                fma2(s_p[i][0], ad[i], bp[0]);
                fma2(s_p[i][1], ad[i], bp[1]);
            }
        }

        float ps[8][4];
        #pragma unroll
        for (int i = 0; i < 8; i++) {
            float t0, t1, t2, t3;
            unpack2(t0, t1, s_p[i][0]);
            unpack2(t2, t3, s_p[i][1]);
            t0 *= SCALE_LOG2E; t1 *= SCALE_LOG2E; t2 *= SCALE_LOG2E; t3 *= SCALE_LOG2E;
            float mloc = fmaxf(fmaxf(t0, t1), fmaxf(t2, t3));
            #pragma unroll
            for (int off = 8; off; off >>= 1)
                mloc = fmaxf(mloc, __shfl_xor_sync(0xffffffffu, mloc, off));
            float newm = fmaxf(mrow[i], mloc);
            float corr = exp2_fast(mrow[i] - newm);
            mrow[i] = newm;
            float p0 = exp2_fast(t0 - newm);
            float p1 = exp2_fast(t1 - newm);
            float p2 = exp2_fast(t2 - newm);
            float p3 = exp2_fast(t3 - newm);
            float rs = (p0 + p1) + (p2 + p3);
            #pragma unroll
            for (int off = 8; off; off >>= 1)
                rs += __shfl_xor_sync(0xffffffffu, rs, off);
            lrow[i] = lrow[i] * corr + rs;
            u64t corrp = dup2(corr);
            mul2(O[i][0], O[i][0], corrp);
            mul2(O[i][1], O[i][1], corrp);
            ps[i][0] = p0; ps[i][1] = p1; ps[i][2] = p2; ps[i][3] = p3;
        }

        #pragma unroll
        for (int j = 0; j < 4; j++) {
            int c = tx * 4 + j;
            float4 p0 = make_float4(ps[0][j], ps[1][j], ps[2][j], ps[3][j]);
            float4 p1 = make_float4(ps[4][j], ps[5][j], ps[6][j], ps[7][j]);
            *(float4*)&Pt[c * QT_STRIDE + ty * 8] = p0;
            *(float4*)&Pt[c * QT_STRIDE + ty * 8 + 4] = p1;
        }
        __syncthreads();

        #pragma unroll 8
        for (int c = 0; c < 64; c++) {
            float4 a0 = *(const float4*)&Pt[c * QT_STRIDE + ty * 8];
            float4 a1 = *(const float4*)&Pt[c * QT_STRIDE + ty * 8 + 4];
            u64t bp[2];
            lds2(bp[0], bp[1], vBase + (unsigned)(c * KT_STRIDE + tx * 4) * 4u);
            u64t ad[8];
            ad[0] = dup2(a0.x); ad[1] = dup2(a0.y);
            ad[2] = dup2(a0.z); ad[3] = dup2(a0.w);
            ad[4] = dup2(a1.x); ad[5] = dup2(a1.y);
            ad[6] = dup2(a1.z); ad[7] = dup2(a1.w);
            #pragma unroll
            for (int i = 0; i < 8; i++) {
                fma2(O[i][0], ad[i], bp[0]);
                fma2(O[i][1], ad[i], bp[1]);
            }
        }
        __syncthreads();
    }

    #pragma unroll
    for (int i = 0; i < 8; i++) {
        float inv = 1.0f / lrow[i];
        float o0, o1, o2, o3;
        unpack2(o0, o1, O[i][0]);
        unpack2(o2, o3, O[i][1]);
        int row = qbase + ty * 8 + i;
        float4 ov = make_float4(o0 * inv, o1 * inv, o2 * inv, o3 * inv);
        *(float4*)&y[(size_t)row * DIM + hoff + tx * 4] = ov;
    }
}

// ---------------- fused residual + LayerNorm ----------------
__global__ void ln_kernel(const float* __restrict__ x, const float* __restrict__ r,
                          const float* __restrict__ w, const float* __restrict__ b,
                          float* __restrict__ out) {
    int row = blockIdx.x;
    int tid = threadIdx.x;
    const float* xr = x + (size_t)row * DIM;
    const float* rr = r + (size_t)row * DIM;
    float vals[4];
    float sum = 0.f;
    #pragma unroll
    for (int i = 0; i < 4; i++) {
        int d = tid + i*128;
        vals[i] = xr[d] + rr[d];
        sum += vals[i];
    }
    __shared__ float red1[4], red2[4];
    #pragma unroll
    for (int off = 16; off; off >>= 1) sum += __shfl_xor_sync(0xffffffffu, sum, off);
    if ((tid & 31) == 0) red1[tid >> 5] = sum;
    __syncthreads();
    sum = red1[0] + red1[1] + red1[2] + red1[3];
    float mean = sum * (1.f / DIM);
    float vs = 0.f;
    #pragma unroll
    for (int i = 0; i < 4; i++) {
        float dv = vals[i] - mean;
        vs += dv * dv;
    }
    #pragma unroll
    for (int off = 16; off; off >>= 1) vs += __shfl_xor_sync(0xffffffffu, vs, off);
    if ((tid & 31) == 0) red2[tid >> 5] = vs;
    __syncthreads();
    vs = red2[0] + red2[1] + red2[2] + red2[3];
    float rstd = rsqrtf(vs * (1.f / DIM) + 1e-5f);
    #pragma unroll
    for (int i = 0; i < 4; i++) {
        int d = tid + i*128;
        out[(size_t)row * DIM + d] = (vals[i] - mean) * rstd * w[d] + b[d];
    }
}

// ---------------- host ----------------
extern "C" void kernel_launch(void* const* d_in, const int* in_sizes, int n_in,
                              void* d_out, int out_size) {
    const float* features = (const float*)d_in[0];
    const float* Wq = (const float*)d_in[1];
    const float* bq = (const float*)d_in[2];
    const float* Wk = (const float*)d_in[3];
    const float* bk = (const float*)d_in[4];
    const float* Wv = (const float*)d_in[5];
    const float* bv = (const float*)d_in[6];
    const float* Wo = (const float*)d_in[7];
    const float* bo = (const float*)d_in[8];
    const float* W1 = (const float*)d_in[9];
    const float* b1 = (const float*)d_in[10];
    const float* W2 = (const float*)d_in[11];
    const float* b2 = (const float*)d_in[12];
    const float* ln1w = (const float*)d_in[13];
    const float* ln1b = (const float*)d_in[14];
    const float* ln2w = (const float*)d_in[15];
    const float* ln2b = (const float*)d_in[16];
    float* out = (float*)d_out;

    float *x, *q, *k, *v, *y, *t, *hbuf;
    __nv_bfloat16 *xh, *xl, *hh, *hl, *wh, *wl;
    cudaGetSymbolAddress((void**)&x, g_x);
    cudaGetSymbolAddress((void**)&q, g_q);
    cudaGetSymbolAddress((void**)&k, g_k);
    cudaGetSymbolAddress((void**)&v, g_v);
    cudaGetSymbolAddress((void**)&y, g_y);
    cudaGetSymbolAddress((void**)&t, g_t);
    cudaGetSymbolAddress((void**)&hbuf, g_h);
    cudaGetSymbolAddress((void**)&xh, g_xh);
    cudaGetSymbolAddress((void**)&xl, g_xl);
    cudaGetSymbolAddress((void**)&hh, g_hh);
    cudaGetSymbolAddress((void**)&hl, g_hl);
    cudaGetSymbolAddress((void**)&wh, g_wh);
    cudaGetSymbolAddress((void**)&wl, g_wl);

    cudaFuncSetAttribute(attn_kernel, cudaFuncAttributeMaxDynamicSharedMemorySize, ATTN_SMEM);
    cudaFuncSetAttribute(mma_gemm<512,0>, cudaFuncAttributeMaxDynamicSharedMemorySize, GEMM_SMEM);
    cudaFuncSetAttribute(mma_gemm<512,1>, cudaFuncAttributeMaxDynamicSharedMemorySize, GEMM_SMEM);
    cudaFuncSetAttribute(mma_gemm<256,0>, cudaFuncAttributeMaxDynamicSharedMemorySize, GEMM_SMEM);

    const size_t OQ = 0, OK = 262144, OV = 524288, OO = 786432, O1 = 1048576, O2 = 1179648;

    for (int l = 0; l < NL; l++) {
        size_t base = (size_t)l * LWSZ;
        transpose_split_kernel<<<(512*512+255)/256, 256>>>(Wq + (size_t)l*DIM*DIM, 512, 512, 512, 512, wh + base + OQ, wl + base + OQ);
        transpose_split_kernel<<<(512*512+255)/256, 256>>>(Wk + (size_t)l*DIM*DIM, 512, 512, 512, 512, wh + base + OK, wl + base + OK);
        transpose_split_kernel<<<(512*512+255)/256, 256>>>(Wv + (size_t)l*DIM*DIM, 512, 512, 512, 512, wh + base + OV, wl + base + OV);
        transpose_split_kernel<<<(512*512+255)/256, 256>>>(Wo + (size_t)l*DIM*DIM, 512, 512, 512, 512, wh + base + OO, wl + base + OO);
        transpose_split_kernel<<<(256*512+255)/256, 256>>>(W1 + (size_t)l*DIM*FF, 512, FF, 512, FFP, wh + base + O1, wl + base + O1);
        transpose_split_kernel<<<(512*256+255)/256, 256>>>(W2 + (size_t)l*FF*DIM, FF, 512, FFP, 512, wh + base + O2, wl + base + O2);
    }

    posenc_kernel<<<(TOK*DIM + 255) / 256, 256>>>(features, x);

    dim3 gD(4, TOK/128);       // N=512 MMA gemms
    dim3 gF1(2, TOK/128);      // N=256(pad) W1
    dim3 gA(SEQ/128, NH, NB);

    for (int l = 0; l < NL; l++) {
        size_t base = (size_t)l * LWSZ;
        split_kernel<<<(TOK*DIM+255)/256, 256>>>(x, xh, xl, TOK*DIM);
        mma_gemm<512,0><<<gD, 256, GEMM_SMEM>>>(xh, xl, wh+base+OQ, wl+base+OQ, bq + l*DIM, q, DIM);
        mma_gemm<512,0><<<gD, 256, GEMM_SMEM>>>(xh, xl, wh+base+OK, wl+base+OK, bk + l*DIM, k, DIM);
        mma_gemm<512,0><<<gD, 256, GEMM_SMEM>>>(xh, xl, wh+base+OV, wl+base+OV, bv + l*DIM, v, DIM);
        attn_kernel<<<gA, 256, ATTN_SMEM>>>(q, k, v, y);
        split_kernel<<<(TOK*DIM+255)/256, 256>>>(y, xh, xl, TOK*DIM);
        mma_gemm<512,0><<<gD, 256, GEMM_SMEM>>>(xh, xl, wh+base+OO, wl+base+OO, bo + l*DIM, t, DIM);
        ln_kernel<<<TOK, 128>>>(x, t, ln1w + l*DIM, ln1b + l*DIM, x);
        split_kernel<<<(TOK*DIM+255)/256, 256>>>(x, xh, xl, TOK*DIM);
        mma_gemm<512,1><<<gF1, 256, GEMM_SMEM>>>(xh, xl, wh+base+O1, wl+base+O1, b1 + l*FF, hbuf, FF);
        split_pad_kernel<<<(TOK*FFP+255)/256, 256>>>(hbuf, hh, hl);
        mma_gemm<256,0><<<gD, 256, GEMM_SMEM>>>(hh, hl, wh+base+O2, wl+base+O2, b2 + l*DIM, t, DIM);
        float* lnout = (l == NL-1) ? out : x;
        ln_kernel<<<TOK, 128>>>(x, t, ln2w + l*DIM, ln2b + l*DIM, lnout);
    }
}

// round 8
// speedup vs baseline: 2.2020x; 1.4672x over previous
#include <cuda_runtime.h>
#include <cuda_bf16.h>
#include <cstdint>

#define TOK 8192
#define SEQ 2048
#define DIM 512
#define NH  8
#define HDM 64
#define NL  4
#define FF  200
#define NB  4
#define FFP 256

// ---------------- device scratch (allocation-free) ----------------
__device__ float g_x[TOK*DIM];
__device__ float g_t[TOK*DIM];
__device__ __nv_bfloat16 g_xh[TOK*DIM];
__device__ __nv_bfloat16 g_xl[TOK*DIM];
__device__ __nv_bfloat16 g_qh[TOK*DIM];
__device__ __nv_bfloat16 g_ql[TOK*DIM];
__device__ __nv_bfloat16 g_kh[TOK*DIM];
__device__ __nv_bfloat16 g_kl[TOK*DIM];
__device__ __nv_bfloat16 g_vh[TOK*DIM];
__device__ __nv_bfloat16 g_vl[TOK*DIM];
__device__ __nv_bfloat16 g_yh[TOK*DIM];
__device__ __nv_bfloat16 g_yl[TOK*DIM];
__device__ __nv_bfloat16 g_hh[TOK*FFP];
__device__ __nv_bfloat16 g_hl[TOK*FFP];
#define LWSZ 1310720
__device__ __nv_bfloat16 g_wh[4*LWSZ];
__device__ __nv_bfloat16 g_wl[4*LWSZ];

// ---------------- helpers ----------------
__device__ __forceinline__ unsigned su32(const void* p) {
    return (unsigned)__cvta_generic_to_shared(p);
}
__device__ __forceinline__ void ldsm4(uint32_t* r, unsigned addr) {
    asm volatile("ldmatrix.sync.aligned.m8n8.x4.shared.b16 {%0,%1,%2,%3}, [%4];"
        : "=r"(r[0]), "=r"(r[1]), "=r"(r[2]), "=r"(r[3]) : "r"(addr));
}
__device__ __forceinline__ void ldsm2(uint32_t* r, unsigned addr) {
    asm volatile("ldmatrix.sync.aligned.m8n8.x2.shared.b16 {%0,%1}, [%2];"
        : "=r"(r[0]), "=r"(r[1]) : "r"(addr));
}
__device__ __forceinline__ void mma16816(float* c, const uint32_t* a, const uint32_t* b) {
    asm volatile("mma.sync.aligned.m16n8k16.row.col.f32.bf16.bf16.f32 "
        "{%0,%1,%2,%3}, {%4,%5,%6,%7}, {%8,%9}, {%0,%1,%2,%3};"
        : "+f"(c[0]), "+f"(c[1]), "+f"(c[2]), "+f"(c[3])
        : "r"(a[0]), "r"(a[1]), "r"(a[2]), "r"(a[3]), "r"(b[0]), "r"(b[1]));
}
// split v into bf16 hi/lo
__device__ __forceinline__ void bsplit(float v, __nv_bfloat16& h, __nv_bfloat16& l) {
    h = __float2bfloat16(v);
    l = __float2bfloat16(v - __bfloat162float(h));
}
__device__ __forceinline__ uint32_t bpack(__nv_bfloat16 a, __nv_bfloat16 b) {
    __nv_bfloat162 p = __nv_bfloat162(a, b);
    return *(uint32_t*)&p;
}

// ---------------- fast exp2 on the FMA pipe (input <= 0) ----------------
__device__ __forceinline__ float exp2_fast(float t) {
    t = fmaxf(t, -126.0f);
    float z = t + 12582912.0f;
    int   ii = __float_as_int(z);
    float n  = z - 12582912.0f;
    float f  = t - n;
    float p  =            1.535336188319500e-4f;
    p = fmaf(p, f, 1.339887440266574e-3f);
    p = fmaf(p, f, 9.618437357674640e-3f);
    p = fmaf(p, f, 5.550332471162809e-2f);
    p = fmaf(p, f, 2.402264791363012e-1f);
    p = fmaf(p, f, 6.931472028550421e-1f);
    p = fmaf(p, f, 1.0f);
    return __int_as_float(__float_as_int(p) + (ii << 23));
}

// ---------------- positional encoding (+fused split) ----------------
__global__ void posenc_kernel(const float* __restrict__ f, float* __restrict__ x,
                              __nv_bfloat16* __restrict__ xh, __nv_bfloat16* __restrict__ xl) {
    int idx = blockIdx.x * blockDim.x + threadIdx.x;
    if (idx >= TOK*DIM) return;
    int d = idx & (DIM-1);
    int s = (idx / DIM) & (SEQ-1);
    int i2 = d & ~1;
    float div = expf((float)i2 * (-9.210340371976184f / (float)DIM));
    float ang = (float)s * div;
    float pe = (d & 1) ? cosf(ang) : sinf(ang);
    float v = f[idx] + pe;
    x[idx] = v;
    __nv_bfloat16 h, l;
    bsplit(v, h, l);
    xh[idx] = h; xl[idx] = l;
}

// W [Kreal,Nreal] -> [Npad][Kpad] hi/lo, zero-padded; layers batched via z
__global__ void transpose_split_kernel(const float* __restrict__ W,
                                       int Kreal, int Nreal, int Kpad, int Npad,
                                       size_t wstride, size_t ostride,
                                       __nv_bfloat16* __restrict__ oh, __nv_bfloat16* __restrict__ ol) {
    int idx = blockIdx.x * blockDim.x + threadIdx.x;
    if (idx >= Npad * Kpad) return;
    const float* Wl = W + (size_t)blockIdx.z * wstride;
    __nv_bfloat16* ohl = oh + (size_t)blockIdx.z * ostride;
    __nv_bfloat16* oll = ol + (size_t)blockIdx.z * ostride;
    int n = idx % Npad, k = idx / Npad;
    float v = (n < Nreal && k < Kreal) ? Wl[(size_t)k * Nreal + n] : 0.f;
    __nv_bfloat16 h, l;
    bsplit(v, h, l);
    ohl[(size_t)n * Kpad + k] = h;
    oll[(size_t)n * Kpad + k] = l;
}

// ---------------- bf16-split GEMM via mma.sync ----------------
// OUTMODE: 0 = fp32 C (Nn==Nreal), 1 = bf16 split C, 2 = bf16 split + relu + pad-zero
#define AST_B 144
#define TILE_B (128 * AST_B)
#define GEMM_SMEM (4 * TILE_B)

template<int KTOT, int OUTMODE>
__global__ __launch_bounds__(256, 2)
void mma_gemm(const __nv_bfloat16* __restrict__ Ah, const __nv_bfloat16* __restrict__ Al,
              const __nv_bfloat16* __restrict__ Bh, const __nv_bfloat16* __restrict__ Bl,
              const float* __restrict__ bias, float* __restrict__ Cf,
              __nv_bfloat16* __restrict__ Ch, __nv_bfloat16* __restrict__ Cl,
              int Nn, int Nreal) {
    extern __shared__ char smem[];
    char* pAh = smem;
    char* pAl = smem + TILE_B;
    char* pBh = smem + 2*TILE_B;
    char* pBl = smem + 3*TILE_B;
    unsigned sAh = su32(pAh), sAl = su32(pAl), sBh = su32(pBh), sBl = su32(pBl);

    int tid = threadIdx.x;
    int wid = tid >> 5, lane = tid & 31;
    int warp_m = wid & 3, warp_n = wid >> 2;
    int m0 = blockIdx.y * 128, n0 = blockIdx.x * 128;

    float acc[2][8][4] = {};

    for (int k0 = 0; k0 < KTOT; k0 += 64) {
        #pragma unroll
        for (int it = 0; it < 4; it++) {
            int chunk = tid + it * 256;
            int r = chunk >> 3;
            int cb = (chunk & 7) * 16;
            size_t ga = ((size_t)(m0 + r) * KTOT + k0) * 2 + cb;
            size_t gb = ((size_t)(n0 + r) * KTOT + k0) * 2 + cb;
            unsigned so = (unsigned)(r * AST_B + cb);
            *(uint4*)(pAh + so) = *(const uint4*)((const char*)Ah + ga);
            *(uint4*)(pAl + so) = *(const uint4*)((const char*)Al + ga);
            *(uint4*)(pBh + so) = *(const uint4*)((const char*)Bh + gb);
            *(uint4*)(pBl + so) = *(const uint4*)((const char*)Bl + gb);
        }
        __syncthreads();

        #pragma unroll
        for (int ks = 0; ks < 4; ks++) {
            int colb = ks * 32;
            uint32_t ah[2][4], al[2][4];
            #pragma unroll
            for (int mt = 0; mt < 2; mt++) {
                unsigned ra = (unsigned)((warp_m*32 + mt*16 + (lane & 15)) * AST_B
                                          + colb + (lane >> 4) * 16);
                ldsm4(ah[mt], sAh + ra);
                ldsm4(al[mt], sAl + ra);
            }
            #pragma unroll
            for (int nt = 0; nt < 8; nt++) {
                unsigned rb = (unsigned)((warp_n*64 + nt*8 + (lane & 7)) * AST_B
                                          + colb + ((lane >> 3) & 1) * 16);
                uint32_t bh[2], bl[2];
                ldsm2(bh, sBh + rb);
                ldsm2(bl, sBl + rb);
                #pragma unroll
                for (int mt = 0; mt < 2; mt++) {
                    mma16816(acc[mt][nt], ah[mt], bh);
                    mma16816(acc[mt][nt], ah[mt], bl);
                    mma16816(acc[mt][nt], al[mt], bh);
                }
            }
        }
        __syncthreads();
    }

    #pragma unroll
    for (int mt = 0; mt < 2; mt++) {
        int r0 = m0 + warp_m*32 + mt*16 + (lane >> 2);
        #pragma unroll
        for (int nt = 0; nt < 8; nt++) {
            int c0 = n0 + warp_n*64 + nt*8 + 2*(lane & 3);
            float b0 = (c0     < Nreal) ? bias[c0]     : 0.f;
            float b1 = (c0 + 1 < Nreal) ? bias[c0 + 1] : 0.f;
            float v0 = acc[mt][nt][0] + b0;
            float v1 = acc[mt][nt][1] + b1;
            float v2 = acc[mt][nt][2] + b0;
            float v3 = acc[mt][nt][3] + b1;
            if (OUTMODE == 0) {
                *(float2*)&Cf[(size_t)r0 * Nn + c0] = make_float2(v0, v1);
                *(float2*)&Cf[(size_t)(r0 + 8) * Nn + c0] = make_float2(v2, v3);
            } else {
                if (OUTMODE == 2) {
                    v0 = (c0     < Nreal) ? fmaxf(v0, 0.f) : 0.f;
                    v1 = (c0 + 1 < Nreal) ? fmaxf(v1, 0.f) : 0.f;
                    v2 = (c0     < Nreal) ? fmaxf(v2, 0.f) : 0.f;
                    v3 = (c0 + 1 < Nreal) ? fmaxf(v3, 0.f) : 0.f;
                }
                __nv_bfloat16 h0,l0,h1,l1,h2,l2,h3,l3;
                bsplit(v0,h0,l0); bsplit(v1,h1,l1); bsplit(v2,h2,l2); bsplit(v3,h3,l3);
                *(uint32_t*)&Ch[(size_t)r0 * Nn + c0] = bpack(h0,h1);
                *(uint32_t*)&Cl[(size_t)r0 * Nn + c0] = bpack(l0,l1);
                *(uint32_t*)&Ch[(size_t)(r0 + 8) * Nn + c0] = bpack(h2,h3);
                *(uint32_t*)&Cl[(size_t)(r0 + 8) * Nn + c0] = bpack(l2,l3);
            }
        }
    }
}

// ---------------- HMMA flash attention ----------------
// grid (SEQ/128, NH, NB), 256 threads. Warp w owns q rows w*16..w*16+15.
#define ATS 72
// smem elem offsets (bf16)
#define SQH 0
#define SQL 9216
#define SKH 18432
#define SKL 23040
#define SVH 27648
#define SVL 32256
#define SPH 36864
#define SPL 46080
#define ATTN_SMEM (55296 * 2)

__global__ __launch_bounds__(256, 1)
void attn_kernel(const __nv_bfloat16* __restrict__ qh, const __nv_bfloat16* __restrict__ ql,
                 const __nv_bfloat16* __restrict__ kh, const __nv_bfloat16* __restrict__ kl,
                 const __nv_bfloat16* __restrict__ vh, const __nv_bfloat16* __restrict__ vl,
                 __nv_bfloat16* __restrict__ yh, __nv_bfloat16* __restrict__ yl) {
    extern __shared__ __nv_bfloat16 smb[];
    unsigned sb = su32(smb);

    int tid = threadIdx.x;
    int wid = tid >> 5, lane = tid & 31;
    int qt_blk = blockIdx.x, h = blockIdx.y, n = blockIdx.z;
    const float SCALE_LOG2E = 0.125f * 1.4426950408889634f;

    int qbase = n * SEQ + qt_blk * 128;
    int hoff = h * HDM;

    // load Q hi/lo [128][64] -> stride ATS
    #pragma unroll
    for (int it = 0; it < 4; it++) {
        int idx = tid + it * 256;                 // over 1024 uint4
        int r = idx >> 3;
        int cb = (idx & 7) * 8;                   // bf16 col
        size_t ga = ((size_t)(qbase + r) * DIM + hoff + cb) * 2;
        *(uint4*)&smb[SQH + r * ATS + cb] = *(const uint4*)((const char*)qh + ga);
        *(uint4*)&smb[SQL + r * ATS + cb] = *(const uint4*)((const char*)ql + ga);
    }

    float o[8][4] = {};
    float m0r = -1e30f, m1r = -1e30f, l0r = 0.f, l1r = 0.f;
    __syncthreads();

    for (int kt = 0; kt < SEQ / 64; kt++) {
        int kbase = n * SEQ + kt * 64;
        // K tiles [64][64]
        #pragma unroll
        for (int it = 0; it < 2; it++) {
            int idx = tid + it * 256;             // over 512 uint4
            int r = idx >> 3;
            int cb = (idx & 7) * 8;
            size_t ga = ((size_t)(kbase + r) * DIM + hoff + cb) * 2;
            *(uint4*)&smb[SKH + r * ATS + cb] = *(const uint4*)((const char*)kh + ga);
            *(uint4*)&smb[SKL + r * ATS + cb] = *(const uint4*)((const char*)kl + ga);
        }
        // V transpose: Vt[d][c]
        #pragma unroll
        for (int it = 0; it < 8; it++) {
            int idx = tid + it * 256;             // over 2048 uint32
            int c = idx >> 5;
            int d0 = (idx & 31) * 2;
            size_t ga = ((size_t)(kbase + c) * DIM + hoff + d0) * 2;
            uint32_t uh = *(const uint32_t*)((const char*)vh + ga);
            uint32_t ul = *(const uint32_t*)((const char*)vl + ga);
            smb[SVH + d0 * ATS + c] = ((__nv_bfloat162*)&uh)->x;
            smb[SVH + (d0+1) * ATS + c] = ((__nv_bfloat162*)&uh)->y;
            smb[SVL + d0 * ATS + c] = ((__nv_bfloat162*)&ul)->x;
            smb[SVL + (d0+1) * ATS + c] = ((__nv_bfloat162*)&ul)->y;
        }
        __syncthreads();

        // S = Q K^T : warp rows wid*16..+15, cols 0..63 (8 nt)
        float s[8][4] = {};
        #pragma unroll
        for (int ks = 0; ks < 4; ks++) {
            int colb = ks * 16 + (lane >> 4) * 8;
            unsigned ra = (unsigned)((wid*16 + (lane & 15)) * ATS + colb) * 2u;
            uint32_t ah[4], al[4];
            ldsm4(ah, sb + SQH*2 + ra);
            ldsm4(al, sb + SQL*2 + ra);
            #pragma unroll
            for (int nt = 0; nt < 8; nt++) {
                unsigned rb = (unsigned)((nt*8 + (lane & 7)) * ATS
                                          + ks*16 + ((lane >> 3) & 1) * 8) * 2u;
                uint32_t bh[2], bl[2];
                ldsm2(bh, sb + SKH*2 + rb);
                ldsm2(bl, sb + SKL*2 + rb);
                mma16816(s[nt], ah, bh);
                mma16816(s[nt], ah, bl);
                mma16816(s[nt], al, bh);
            }
        }

        // online softmax: rows r0 = wid*16 + (lane>>2), r1 = r0+8
        float mx0 = -1e30f, mx1 = -1e30f;
        #pragma unroll
        for (int nt = 0; nt < 8; nt++) {
            s[nt][0] *= SCALE_LOG2E; s[nt][1] *= SCALE_LOG2E;
            s[nt][2] *= SCALE_LOG2E; s[nt][3] *= SCALE_LOG2E;
            mx0 = fmaxf(mx0, fmaxf(s[nt][0], s[nt][1]));
            mx1 = fmaxf(mx1, fmaxf(s[nt][2], s[nt][3]));
        }
        mx0 = fmaxf(mx0, __shfl_xor_sync(0xffffffffu, mx0, 1));
        mx0 = fmaxf(mx0, __shfl_xor_sync(0xffffffffu, mx0, 2));
        mx1 = fmaxf(mx1, __shfl_xor_sync(0xffffffffu, mx1, 1));
        mx1 = fmaxf(mx1, __shfl_xor_sync(0xffffffffu, mx1, 2));
        float nm0 = fmaxf(m0r, mx0), nm1 = fmaxf(m1r, mx1);
        float corr0 = exp2_fast(m0r - nm0), corr1 = exp2_fast(m1r - nm1);
        m0r = nm0; m1r = nm1;
        float rs0 = 0.f, rs1 = 0.f;
        int r0 = wid*16 + (lane >> 2);
        int pc = 2 * (lane & 3);
        #pragma unroll
        for (int nt = 0; nt < 8; nt++) {
            float p0 = exp2_fast(s[nt][0] - nm0);
            float p1 = exp2_fast(s[nt][1] - nm0);
            float p2 = exp2_fast(s[nt][2] - nm1);
            float p3 = exp2_fast(s[nt][3] - nm1);
            rs0 += p0 + p1; rs1 += p2 + p3;
            o[nt][0] *= corr0; o[nt][1] *= corr0;
            o[nt][2] *= corr1; o[nt][3] *= corr1;
            __nv_bfloat16 h0,l0,h1,l1,h2,l2,h3,l3;
            bsplit(p0,h0,l0); bsplit(p1,h1,l1); bsplit(p2,h2,l2); bsplit(p3,h3,l3);
            *(uint32_t*)&smb[SPH + r0 * ATS + nt*8 + pc] = bpack(h0,h1);
            *(uint32_t*)&smb[SPL + r0 * ATS + nt*8 + pc] = bpack(l0,l1);
            *(uint32_t*)&smb[SPH + (r0+8) * ATS + nt*8 + pc] = bpack(h2,h3);
            *(uint32_t*)&smb[SPL + (r0+8) * ATS + nt*8 + pc] = bpack(l2,l3);
        }
        rs0 += __shfl_xor_sync(0xffffffffu, rs0, 1);
        rs0 += __shfl_xor_sync(0xffffffffu, rs0, 2);
        rs1 += __shfl_xor_sync(0xffffffffu, rs1, 1);
        rs1 += __shfl_xor_sync(0xffffffffu, rs1, 2);
        l0r = l0r * corr0 + rs0;
        l1r = l1r * corr1 + rs1;
        __syncthreads();

        // O += P @ V : A = P rows, B = Vt[d][c]
        #pragma unroll
        for (int ks = 0; ks < 4; ks++) {
            int colb = ks * 16 + (lane >> 4) * 8;
            unsigned ra = (unsigned)((wid*16 + (lane & 15)) * ATS + colb) * 2u;
            uint32_t ah[4], al[4];
            ldsm4(ah, sb + SPH*2 + ra);
            ldsm4(al, sb + SPL*2 + ra);
            #pragma unroll
            for (int nt = 0; nt < 8; nt++) {
                unsigned rb = (unsigned)((nt*8 + (lane & 7)) * ATS
                                          + ks*16 + ((lane >> 3) & 1) * 8) * 2u;
                uint32_t bh[2], bl[2];
                ldsm2(bh, sb + SVH*2 + rb);
                ldsm2(bl, sb + SVL*2 + rb);
                mma16816(o[nt], ah, bh);
                mma16816(o[nt], ah, bl);
                mma16816(o[nt], al, bh);
            }
        }
        __syncthreads();
    }

    // epilogue: normalize + split-store y
    float inv0 = 1.f / l0r, inv1 = 1.f / l1r;
    int r0 = qbase + wid*16 + (lane >> 2);
    int c0 = hoff + 2 * (lane & 3);
    #pragma unroll
    for (int nt = 0; nt < 8; nt++) {
        float v0 = o[nt][0] * inv0, v1 = o[nt][1] * inv0;
        float v2 = o[nt][2] * inv1, v3 = o[nt][3] * inv1;
        __nv_bfloat16 h0,l0,h1,l1,h2,l2,h3,l3;
        bsplit(v0,h0,l0); bsplit(v1,h1,l1); bsplit(v2,h2,l2); bsplit(v3,h3,l3);
        *(uint32_t*)&yh[(size_t)r0 * DIM + c0 + nt*8] = bpack(h0,h1);
        *(uint32_t*)&yl[(size_t)r0 * DIM + c0 + nt*8] = bpack(l0,l1);
        *(uint32_t*)&yh[(size_t)(r0+8) * DIM + c0 + nt*8] = bpack(h2,h3);
        *(uint32_t*)&yl[(size_t)(r0+8) * DIM + c0 + nt*8] = bpack(l2,l3);
    }
}

// ---------------- fused residual + LayerNorm (+split out) ----------------
__global__ void ln_kernel(const float* __restrict__ x, const float* __restrict__ r,
                          const float* __restrict__ w, const float* __restrict__ b,
                          float* __restrict__ out,
                          __nv_bfloat16* __restrict__ oh, __nv_bfloat16* __restrict__ ol) {
    int row = blockIdx.x;
    int tid = threadIdx.x;
    const float* xr = x + (size_t)row * DIM;
    const float* rr = r + (size_t)row * DIM;
    float vals[4];
    float sum = 0.f;
    #pragma unroll
    for (int i = 0; i < 4; i++) {
        int d = tid + i*128;
        vals[i] = xr[d] + rr[d];
        sum += vals[i];
    }
    __shared__ float red1[4], red2[4];
    #pragma unroll
    for (int off = 16; off; off >>= 1) sum += __shfl_xor_sync(0xffffffffu, sum, off);
    if ((tid & 31) == 0) red1[tid >> 5] = sum;
    __syncthreads();
    sum = red1[0] + red1[1] + red1[2] + red1[3];
    float mean = sum * (1.f / DIM);
    float vs = 0.f;
    #pragma unroll
    for (int i = 0; i < 4; i++) {
        float dv = vals[i] - mean;
        vs += dv * dv;
    }
    #pragma unroll
    for (int off = 16; off; off >>= 1) vs += __shfl_xor_sync(0xffffffffu, vs, off);
    if ((tid & 31) == 0) red2[tid >> 5] = vs;
    __syncthreads();
    vs = red2[0] + red2[1] + red2[2] + red2[3];
    float rstd = rsqrtf(vs * (1.f / DIM) + 1e-5f);
    #pragma unroll
    for (int i = 0; i < 4; i++) {
        int d = tid + i*128;
        float v = (vals[i] - mean) * rstd * w[d] + b[d];
        out[(size_t)row * DIM + d] = v;
        __nv_bfloat16 h, l;
        bsplit(v, h, l);
        oh[(size_t)row * DIM + d] = h;
        ol[(size_t)row * DIM + d] = l;
    }
}

// ---------------- host ----------------
extern "C" void kernel_launch(void* const* d_in, const int* in_sizes, int n_in,
                              void* d_out, int out_size) {
    const float* features = (const float*)d_in[0];
    const float* Wq = (const float*)d_in[1];
    const float* bq = (const float*)d_in[2];
    const float* Wk = (const float*)d_in[3];
    const float* bk = (const float*)d_in[4];
    const float* Wv = (const float*)d_in[5];
    const float* bv = (const float*)d_in[6];
    const float* Wo = (const float*)d_in[7];
    const float* bo = (const float*)d_in[8];
    const float* W1 = (const float*)d_in[9];
    const float* b1 = (const float*)d_in[10];
    const float* W2 = (const float*)d_in[11];
    const float* b2 = (const float*)d_in[12];
    const float* ln1w = (const float*)d_in[13];
    const float* ln1b = (const float*)d_in[14];
    const float* ln2w = (const float*)d_in[15];
    const float* ln2b = (const float*)d_in[16];
    float* out = (float*)d_out;

    float *x, *t;
    __nv_bfloat16 *xh, *xl, *qh, *ql, *kh, *kl, *vh, *vl, *yh, *yl, *hh, *hl, *wh, *wl;
    cudaGetSymbolAddress((void**)&x, g_x);
    cudaGetSymbolAddress((void**)&t, g_t);
    cudaGetSymbolAddress((void**)&xh, g_xh);
    cudaGetSymbolAddress((void**)&xl, g_xl);
    cudaGetSymbolAddress((void**)&qh, g_qh);
    cudaGetSymbolAddress((void**)&ql, g_ql);
    cudaGetSymbolAddress((void**)&kh, g_kh);
    cudaGetSymbolAddress((void**)&kl, g_kl);
    cudaGetSymbolAddress((void**)&vh, g_vh);
    cudaGetSymbolAddress((void**)&vl, g_vl);
    cudaGetSymbolAddress((void**)&yh, g_yh);
    cudaGetSymbolAddress((void**)&yl, g_yl);
    cudaGetSymbolAddress((void**)&hh, g_hh);
    cudaGetSymbolAddress((void**)&hl, g_hl);
    cudaGetSymbolAddress((void**)&wh, g_wh);
    cudaGetSymbolAddress((void**)&wl, g_wl);

    cudaFuncSetAttribute(attn_kernel, cudaFuncAttributeMaxDynamicSharedMemorySize, ATTN_SMEM);
    cudaFuncSetAttribute(mma_gemm<512,0>, cudaFuncAttributeMaxDynamicSharedMemorySize, GEMM_SMEM);
    cudaFuncSetAttribute(mma_gemm<512,1>, cudaFuncAttributeMaxDynamicSharedMemorySize, GEMM_SMEM);
    cudaFuncSetAttribute(mma_gemm<512,2>, cudaFuncAttributeMaxDynamicSharedMemorySize, GEMM_SMEM);
    cudaFuncSetAttribute(mma_gemm<256,0>, cudaFuncAttributeMaxDynamicSharedMemorySize, GEMM_SMEM);

    const size_t OQ = 0, OK = 262144, OV = 524288, OO = 786432, O1 = 1048576, O2 = 1179648;

    // batched weight prep (z = layer)
    dim3 gW((512*512+255)/256, 1, NL);
    dim3 gW1((256*512+255)/256, 1, NL);
    transpose_split_kernel<<<gW, 256>>>(Wq, 512, 512, 512, 512, (size_t)DIM*DIM, LWSZ, wh + OQ, wl + OQ);
    transpose_split_kernel<<<gW, 256>>>(Wk, 512, 512, 512, 512, (size_t)DIM*DIM, LWSZ, wh + OK, wl + OK);
    transpose_split_kernel<<<gW, 256>>>(Wv, 512, 512, 512, 512, (size_t)DIM*DIM, LWSZ, wh + OV, wl + OV);
    transpose_split_kernel<<<gW, 256>>>(Wo, 512, 512, 512, 512, (size_t)DIM*DIM, LWSZ, wh + OO, wl + OO);
    transpose_split_kernel<<<gW1, 256>>>(W1, 512, FF, 512, FFP, (size_t)DIM*FF, LWSZ, wh + O1, wl + O1);
    transpose_split_kernel<<<gW1, 256>>>(W2, FF, 512, FFP, 512, (size_t)FF*DIM, LWSZ, wh + O2, wl + O2);

    posenc_kernel<<<(TOK*DIM + 255) / 256, 256>>>(features, x, xh, xl);

    dim3 gD(4, TOK/128);
    dim3 gF1(2, TOK/128);
    dim3 gA(SEQ/128, NH, NB);

    for (int l = 0; l < NL; l++) {
        size_t base = (size_t)l * LWSZ;
        mma_gemm<512,1><<<gD, 256, GEMM_SMEM>>>(xh, xl, wh+base+OQ, wl+base+OQ, bq + l*DIM, nullptr, qh, ql, DIM, DIM);
        mma_gemm<512,1><<<gD, 256, GEMM_SMEM>>>(xh, xl, wh+base+OK, wl+base+OK, bk + l*DIM, nullptr, kh, kl, DIM, DIM);
        mma_gemm<512,1><<<gD, 256, GEMM_SMEM>>>(xh, xl, wh+base+OV, wl+base+OV, bv + l*DIM, nullptr, vh, vl, DIM, DIM);
        attn_kernel<<<gA, 256, ATTN_SMEM>>>(qh, ql, kh, kl, vh, vl, yh, yl);
        mma_gemm<512,0><<<gD, 256, GEMM_SMEM>>>(yh, yl, wh+base+OO, wl+base+OO, bo + l*DIM, t, nullptr, nullptr, DIM, DIM);
        ln_kernel<<<TOK, 128>>>(x, t, ln1w + l*DIM, ln1b + l*DIM, x, xh, xl);
        mma_gemm<512,2><<<gF1, 256, GEMM_SMEM>>>(xh, xl, wh+base+O1, wl+base+O1, b1 + l*FF, nullptr, hh, hl, FFP, FF);
        mma_gemm<256,0><<<gD, 256, GEMM_SMEM>>>(hh, hl, wh+base+O2, wl+base+O2, b2 + l*DIM, t, nullptr, nullptr, DIM, DIM);
        float* lnout = (l == NL-1) ? out : x;
        ln_kernel<<<TOK, 128>>>(x, t, ln2w + l*DIM, ln2b + l*DIM, lnout, xh, xl);
    }
}